// round 1
// baseline (speedup 1.0000x reference)
#include <cuda_runtime.h>
#include <math.h>

// ---------------- scratch (static device memory; no allocations) ----------------
// qkv: [4096, 6144]   q/k/v head-major: [b=2, h=16, s=2048, d=128] = 4096*2048
// att: [b=2, s=2048, d_model=2048]
__device__ float g_qkv[4096 * 6144];
__device__ float g_q[4096 * 2048];
__device__ float g_k[4096 * 2048];
__device__ float g_v[4096 * 2048];
__device__ float g_att[4096 * 2048];

// ---------------- SGEMM with bias: C[M,N] = A[M,K] @ B[K,N] + bias[N] ----------------
// BM=BN=128, BK=16, 256 threads, 8x8 microtile per thread. M,N % 128 == 0, K % 16 == 0.
__global__ __launch_bounds__(256) void sgemm_bias(
    const float* __restrict__ A, const float* __restrict__ B,
    const float* __restrict__ bias, float* __restrict__ C,
    int M, int N, int K)
{
    __shared__ float As[16][128];
    __shared__ float Bs[16][128];

    const int tid = threadIdx.x;
    const int tx = tid & 15;          // 0..15  (N dir)
    const int ty = tid >> 4;          // 0..15  (M dir)
    const int bm = blockIdx.y * 128;
    const int bn = blockIdx.x * 128;

    const float* Ag = A + (size_t)bm * K;
    const float* Bg = B + bn;

    float acc[8][8];
#pragma unroll
    for (int i = 0; i < 8; i++)
#pragma unroll
        for (int j = 0; j < 8; j++) acc[i][j] = 0.0f;

    // A tile load coords: 128 rows x 16 cols = 512 float4, 2 per thread
    const int a_row = tid >> 2;            // 0..63 (second half +64)
    const int a_kc  = (tid & 3) * 4;       // 0,4,8,12
    // B tile load coords: 16 rows x 128 cols = 512 float4, 2 per thread
    const int b_row = tid >> 5;            // 0..7 (second +8)
    const int b_c   = (tid & 31) * 4;      // 0..124

    for (int k0 = 0; k0 < K; k0 += 16) {
        float4 a0 = *(const float4*)&Ag[(size_t)a_row * K + k0 + a_kc];
        float4 a1 = *(const float4*)&Ag[(size_t)(a_row + 64) * K + k0 + a_kc];
        float4 b0 = *(const float4*)&Bg[(size_t)(k0 + b_row) * N + b_c];
        float4 b1 = *(const float4*)&Bg[(size_t)(k0 + b_row + 8) * N + b_c];

        __syncthreads();
        As[a_kc + 0][a_row] = a0.x;
        As[a_kc + 1][a_row] = a0.y;
        As[a_kc + 2][a_row] = a0.z;
        As[a_kc + 3][a_row] = a0.w;
        As[a_kc + 0][a_row + 64] = a1.x;
        As[a_kc + 1][a_row + 64] = a1.y;
        As[a_kc + 2][a_row + 64] = a1.z;
        As[a_kc + 3][a_row + 64] = a1.w;
        *(float4*)&Bs[b_row][b_c]     = b0;
        *(float4*)&Bs[b_row + 8][b_c] = b1;
        __syncthreads();

#pragma unroll
        for (int k = 0; k < 16; k++) {
            float ar[8], br[8];
            *(float4*)&ar[0] = *(const float4*)&As[k][ty * 8];
            *(float4*)&ar[4] = *(const float4*)&As[k][ty * 8 + 4];
            *(float4*)&br[0] = *(const float4*)&Bs[k][tx * 8];
            *(float4*)&br[4] = *(const float4*)&Bs[k][tx * 8 + 4];
#pragma unroll
            for (int i = 0; i < 8; i++)
#pragma unroll
                for (int j = 0; j < 8; j++)
                    acc[i][j] = fmaf(ar[i], br[j], acc[i][j]);
        }
    }

#pragma unroll
    for (int i = 0; i < 8; i++) {
        const int row = bm + ty * 8 + i;
#pragma unroll
        for (int j = 0; j < 8; j += 4) {
            const int col = bn + tx * 8 + j;
            float4 o;
            o.x = acc[i][j + 0] + bias[col + 0];
            o.y = acc[i][j + 1] + bias[col + 1];
            o.z = acc[i][j + 2] + bias[col + 2];
            o.w = acc[i][j + 3] + bias[col + 3];
            *(float4*)&C[(size_t)row * N + col] = o;
        }
    }
}

// ---------------- RoPE + split into head-major Q/K/V ----------------
// one thread per (b, h, s, i) pair, i in [0,64)
__global__ void rope_split_kernel(const float* __restrict__ qkv)
{
    const int idx = blockIdx.x * blockDim.x + threadIdx.x; // < 2*16*2048*64
    const int i = idx & 63;
    const int s = (idx >> 6) & 2047;
    const int h = (idx >> 17) & 15;
    const int b = idx >> 21;

    const size_t row = (size_t)(b * 2048 + s) * 6144;
    const int c = h * 128 + 2 * i;

    // theta = 1 / 10000^{(2i)/128}   (match jax f32 path)
    const float theta = 1.0f / powf(10000.0f, (float)(2 * i) / 128.0f);
    const float ang = (float)s * theta;
    float sn, cs;
    sincosf(ang, &sn, &cs);

    const float q0 = qkv[row + c],        q1 = qkv[row + c + 1];
    const float k0 = qkv[row + 2048 + c], k1 = qkv[row + 2048 + c + 1];
    const float v0 = qkv[row + 4096 + c], v1 = qkv[row + 4096 + c + 1];

    const size_t ob = ((size_t)(b * 16 + h) * 2048 + s) * 128;
    g_q[ob + i]      = q0 * cs - q1 * sn;
    g_q[ob + 64 + i] = q0 * sn + q1 * cs;
    g_k[ob + i]      = k0 * cs - k1 * sn;
    g_k[ob + 64 + i] = k0 * sn + k1 * cs;
    g_v[ob + 2 * i]     = v0;
    g_v[ob + 2 * i + 1] = v1;
}

// ---------------- Flash attention (fp32, online softmax) ----------------
// grid: (s/128, b*h), 128 threads. Thread t owns query row t of the tile.
// smem: Q tile 128x132 (padded), K/V chunks 32x128 each.
#define ATTN_QS 132
#define ATTN_BN 32
#define ATTN_SMEM_FLOATS (128 * ATTN_QS + 2 * ATTN_BN * 128)
#define ATTN_SMEM_BYTES  (ATTN_SMEM_FLOATS * 4)

__global__ __launch_bounds__(128, 2) void attn_kernel(float* __restrict__ Oatt)
{
    extern __shared__ float smem[];
    float* sq = smem;                       // 128 * 132
    float* sk = smem + 128 * ATTN_QS;       // 32 * 128
    float* sv = sk + ATTN_BN * 128;         // 32 * 128

    const int tid = threadIdx.x;
    const int bh = blockIdx.y;
    const int qb = blockIdx.x;

    const float* Qp = g_q + (size_t)bh * 2048 * 128 + (size_t)qb * 128 * 128;
    const float* Kp = g_k + (size_t)bh * 2048 * 128;
    const float* Vp = g_v + (size_t)bh * 2048 * 128;

    // load Q tile (16384 floats = 4096 float4)
    for (int it = tid; it < 4096; it += 128) {
        float4 qv = *(const float4*)&Qp[it * 4];
        const int r = (it * 4) >> 7;
        const int d = (it * 4) & 127;
        *(float4*)&sq[r * ATTN_QS + d] = qv;
    }

    float acc[128];
#pragma unroll
    for (int d = 0; d < 128; d++) acc[d] = 0.0f;
    float m = -1e30f;
    float l = 0.0f;
    const float scale = 0.08838834764831845f; // 1/sqrt(128)

    for (int kc = 0; kc < 2048; kc += ATTN_BN) {
        __syncthreads();
        // load K,V chunk: 32*128 floats = 1024 float4 each
        for (int it = tid; it < ATTN_BN * 32; it += 128) {
            *(float4*)&sk[it * 4] = *(const float4*)&Kp[(size_t)kc * 128 + it * 4];
            *(float4*)&sv[it * 4] = *(const float4*)&Vp[(size_t)kc * 128 + it * 4];
        }
        __syncthreads();

#pragma unroll 2
        for (int j = 0; j < ATTN_BN; j++) {
            float s0 = 0.f, s1 = 0.f, s2 = 0.f, s3 = 0.f;
#pragma unroll
            for (int d4 = 0; d4 < 32; d4++) {
                float4 kq = *(const float4*)&sk[j * 128 + d4 * 4];
                float4 qq = *(const float4*)&sq[tid * ATTN_QS + d4 * 4];
                s0 = fmaf(qq.x, kq.x, s0);
                s1 = fmaf(qq.y, kq.y, s1);
                s2 = fmaf(qq.z, kq.z, s2);
                s3 = fmaf(qq.w, kq.w, s3);
            }
            const float sc = (s0 + s1 + s2 + s3) * scale;

            if (sc > m) {
                const float alpha = __expf(m - sc);
                m = sc;
                l = fmaf(l, alpha, 1.0f);
#pragma unroll
                for (int d4 = 0; d4 < 32; d4++) {
                    float4 vv = *(const float4*)&sv[j * 128 + d4 * 4];
                    acc[d4 * 4 + 0] = fmaf(acc[d4 * 4 + 0], alpha, vv.x);
                    acc[d4 * 4 + 1] = fmaf(acc[d4 * 4 + 1], alpha, vv.y);
                    acc[d4 * 4 + 2] = fmaf(acc[d4 * 4 + 2], alpha, vv.z);
                    acc[d4 * 4 + 3] = fmaf(acc[d4 * 4 + 3], alpha, vv.w);
                }
            } else {
                const float p = __expf(sc - m);
                l += p;
#pragma unroll
                for (int d4 = 0; d4 < 32; d4++) {
                    float4 vv = *(const float4*)&sv[j * 128 + d4 * 4];
                    acc[d4 * 4 + 0] = fmaf(p, vv.x, acc[d4 * 4 + 0]);
                    acc[d4 * 4 + 1] = fmaf(p, vv.y, acc[d4 * 4 + 1]);
                    acc[d4 * 4 + 2] = fmaf(p, vv.z, acc[d4 * 4 + 2]);
                    acc[d4 * 4 + 3] = fmaf(p, vv.w, acc[d4 * 4 + 3]);
                }
            }
        }
    }

    const float inv_l = 1.0f / l;
    const int b = bh >> 4;
    const int h = bh & 15;
    const int srow = qb * 128 + tid;
    float* Op = Oatt + (size_t)(b * 2048 + srow) * 2048 + h * 128;
#pragma unroll
    for (int d4 = 0; d4 < 32; d4++) {
        float4 o;
        o.x = acc[d4 * 4 + 0] * inv_l;
        o.y = acc[d4 * 4 + 1] * inv_l;
        o.z = acc[d4 * 4 + 2] * inv_l;
        o.w = acc[d4 * 4 + 3] * inv_l;
        *(float4*)&Op[d4 * 4] = o;
    }
}

// ---------------- launch ----------------
extern "C" void kernel_launch(void* const* d_in, const int* in_sizes, int n_in,
                              void* d_out, int out_size)
{
    const float* x    = (const float*)d_in[0]; // [2,2048,2048]
    const float* Wqkv = (const float*)d_in[1]; // [2048,6144]
    const float* bqkv = (const float*)d_in[2]; // [6144]
    const float* Wo   = (const float*)d_in[3]; // [2048,2048]
    const float* bo   = (const float*)d_in[4]; // [2048]
    float* out = (float*)d_out;                // [2,2048,2048]

    float *qkv, *att;
    cudaGetSymbolAddress((void**)&qkv, g_qkv);
    cudaGetSymbolAddress((void**)&att, g_att);

    // 1) QKV projection: [4096,2048] @ [2048,6144] + bqkv
    sgemm_bias<<<dim3(6144 / 128, 4096 / 128), 256>>>(x, Wqkv, bqkv, qkv, 4096, 6144, 2048);

    // 2) RoPE + head split
    rope_split_kernel<<<(2 * 16 * 2048 * 64) / 256, 256>>>(qkv);

    // 3) Flash attention
    cudaFuncSetAttribute(attn_kernel, cudaFuncAttributeMaxDynamicSharedMemorySize,
                         ATTN_SMEM_BYTES);
    attn_kernel<<<dim3(2048 / 128, 2 * 16), 128, ATTN_SMEM_BYTES>>>(att);

    // 4) Output projection: [4096,2048] @ [2048,2048] + bo
    sgemm_bias<<<dim3(2048 / 128, 4096 / 128), 256>>>(att, Wo, bo, out, 4096, 2048, 2048);
}

// round 3
// speedup vs baseline: 1.5566x; 1.5566x over previous
#include <cuda_runtime.h>
#include <cuda_bf16.h>
#include <cstdint>
#include <math.h>

// ================= scratch =================
__device__ float g_qkv[4096 * 6144];
__device__ float g_q[4096 * 2048];
__device__ float g_k[4096 * 2048];
__device__ float g_v[4096 * 2048];
__device__ __nv_bfloat16 g_x_hi[4096 * 2048];
__device__ __nv_bfloat16 g_x_lo[4096 * 2048];
__device__ __nv_bfloat16 g_att_hi[4096 * 2048];
__device__ __nv_bfloat16 g_att_lo[4096 * 2048];
__device__ __nv_bfloat16 g_WqkvT_hi[6144 * 2048];
__device__ __nv_bfloat16 g_WqkvT_lo[6144 * 2048];
__device__ __nv_bfloat16 g_WoT_hi[2048 * 2048];
__device__ __nv_bfloat16 g_WoT_lo[2048 * 2048];

// ================= helpers =================
__device__ __forceinline__ uint32_t smem_u32(const void* p) {
    uint32_t a;
    asm("{ .reg .u64 t; cvta.to.shared.u64 t, %1; cvt.u32.u64 %0, t; }" : "=r"(a) : "l"(p));
    return a;
}
__device__ __forceinline__ void ldsm4(uint32_t (&r)[4], uint32_t addr) {
    asm volatile("ldmatrix.sync.aligned.m8n8.x4.shared.b16 {%0,%1,%2,%3}, [%4];"
        : "=r"(r[0]), "=r"(r[1]), "=r"(r[2]), "=r"(r[3]) : "r"(addr));
}
__device__ __forceinline__ void mma16816(float* c, const uint32_t* a, const uint32_t* b) {
    asm volatile("mma.sync.aligned.m16n8k16.row.col.f32.bf16.bf16.f32 "
        "{%0,%1,%2,%3}, {%4,%5,%6,%7}, {%8,%9}, {%0,%1,%2,%3};"
        : "+f"(c[0]), "+f"(c[1]), "+f"(c[2]), "+f"(c[3])
        : "r"(a[0]), "r"(a[1]), "r"(a[2]), "r"(a[3]), "r"(b[0]), "r"(b[1]));
}

// ================= prep kernels =================
__global__ void split_convert(const float* __restrict__ in,
                              __nv_bfloat16* __restrict__ hi, __nv_bfloat16* __restrict__ lo, int n) {
    int i = blockIdx.x * blockDim.x + threadIdx.x;
    if (i >= n) return;
    float v = in[i];
    __nv_bfloat16 h = __float2bfloat16(v);
    hi[i] = h;
    lo[i] = __float2bfloat16(v - __bfloat162float(h));
}

// W[K,N] row-major -> WT[N,K] bf16 hi/lo
__global__ void transpose_split(const float* __restrict__ W,
                                __nv_bfloat16* __restrict__ Thi, __nv_bfloat16* __restrict__ Tlo,
                                int K, int N) {
    __shared__ float s[32][33];
    int n0 = blockIdx.x * 32, k0 = blockIdx.y * 32;
    int tx = threadIdx.x, ty = threadIdx.y;
#pragma unroll
    for (int j = 0; j < 32; j += 8)
        s[ty + j][tx] = W[(size_t)(k0 + ty + j) * N + n0 + tx];
    __syncthreads();
#pragma unroll
    for (int j = 0; j < 32; j += 8) {
        float v = s[tx][ty + j];
        __nv_bfloat16 h = __float2bfloat16(v);
        size_t o = (size_t)(n0 + ty + j) * K + k0 + tx;
        Thi[o] = h;
        Tlo[o] = __float2bfloat16(v - __bfloat162float(h));
    }
}

// ================= tensor-core GEMM via mma.sync =================
// C[M,N] = A[M,K] @ B[K,N] + bias, A as bf16 hi/lo [M,K], B transposed bf16 hi/lo [N,K].
// BM=BN=128, BK=32. 256 threads, warp grid 2(M)x4(N), warp tile 64x32.
// smem rows padded to 80B (32 bf16 + 16B) -> conflict-free ldmatrix.
#define STG_A   0
#define STG_AL  10240
#define STG_B   20480
#define STG_BL  30720
#define STG_BYTES 40960
#define G_SMEM (2 * STG_BYTES)

__device__ __forceinline__ void gemm_load_chunk(
    uint4* rg,
    const __nv_bfloat16* __restrict__ Ah, const __nv_bfloat16* __restrict__ Al,
    const __nv_bfloat16* __restrict__ Bh, const __nv_bfloat16* __restrict__ Bl,
    int bm, int bn, int K, int kc, int tid)
{
    const int i0 = tid, i1 = tid + 256;
    const int r0 = i0 >> 2, c0 = (i0 & 3) * 8;
    const int r1 = i1 >> 2, c1 = (i1 & 3) * 8;
    rg[0] = *(const uint4*)(Ah + (size_t)(bm + r0) * K + kc + c0);
    rg[1] = *(const uint4*)(Ah + (size_t)(bm + r1) * K + kc + c1);
    rg[2] = *(const uint4*)(Al + (size_t)(bm + r0) * K + kc + c0);
    rg[3] = *(const uint4*)(Al + (size_t)(bm + r1) * K + kc + c1);
    rg[4] = *(const uint4*)(Bh + (size_t)(bn + r0) * K + kc + c0);
    rg[5] = *(const uint4*)(Bh + (size_t)(bn + r1) * K + kc + c1);
    rg[6] = *(const uint4*)(Bl + (size_t)(bn + r0) * K + kc + c0);
    rg[7] = *(const uint4*)(Bl + (size_t)(bn + r1) * K + kc + c1);
}

__device__ __forceinline__ void gemm_store_chunk(char* stage, const uint4* rg, int tid)
{
    const int i0 = tid, i1 = tid + 256;
    const int o0 = (i0 >> 2) * 80 + (i0 & 3) * 16;
    const int o1 = (i1 >> 2) * 80 + (i1 & 3) * 16;
    *(uint4*)(stage + STG_A  + o0) = rg[0];
    *(uint4*)(stage + STG_A  + o1) = rg[1];
    *(uint4*)(stage + STG_AL + o0) = rg[2];
    *(uint4*)(stage + STG_AL + o1) = rg[3];
    *(uint4*)(stage + STG_B  + o0) = rg[4];
    *(uint4*)(stage + STG_B  + o1) = rg[5];
    *(uint4*)(stage + STG_BL + o0) = rg[6];
    *(uint4*)(stage + STG_BL + o1) = rg[7];
}

__global__ __launch_bounds__(256) void gemm_tc(
    const __nv_bfloat16* __restrict__ Ah, const __nv_bfloat16* __restrict__ Al,
    const __nv_bfloat16* __restrict__ Bh, const __nv_bfloat16* __restrict__ Bl,
    const float* __restrict__ bias, float* __restrict__ C, int N, int K)
{
    extern __shared__ char smem[];
    const int tid = threadIdx.x;
    const int lane = tid & 31;
    const int wid = tid >> 5;
    const int wm = wid & 1;       // 0..1 : M direction (64 rows)
    const int wn = wid >> 1;      // 0..3 : N direction (32 cols)
    const int bm = blockIdx.y * 128;
    const int bn = blockIdx.x * 128;

    float acc[4][4][4];
#pragma unroll
    for (int i = 0; i < 4; i++)
#pragma unroll
        for (int j = 0; j < 4; j++)
#pragma unroll
            for (int k = 0; k < 4; k++) acc[i][j][k] = 0.0f;

    // ldmatrix lane address offsets (within stage)
    const uint32_t sb0 = smem_u32(smem);
    // A: lanes 0-15 -> rows (lane&15) @k0 ; lanes 16-31 -> rows (lane&15) @k+8
    const uint32_t aOff = (uint32_t)((wm * 64 + (lane & 15)) * 80 + ((lane >> 4) << 4));
    // B: lanes 0-7 n0-7@k0 ; 8-15 n0-7@k8 ; 16-23 n8-15@k0 ; 24-31 n8-15@k8
    const uint32_t bOff = (uint32_t)((wn * 32 + (lane & 7) + ((lane >> 4) << 3)) * 80
                                     + (((lane >> 3) & 1) << 4));

    const int nch = K / 32;
    uint4 rg[8];
    gemm_load_chunk(rg, Ah, Al, Bh, Bl, bm, bn, K, 0, tid);
    gemm_store_chunk(smem, rg, tid);
    __syncthreads();

    for (int c = 0; c < nch; c++) {
        if (c + 1 < nch)
            gemm_load_chunk(rg, Ah, Al, Bh, Bl, bm, bn, K, (c + 1) * 32, tid);

        const uint32_t sb = sb0 + (uint32_t)((c & 1) * STG_BYTES);
#pragma unroll
        for (int ks = 0; ks < 2; ks++) {
            const uint32_t ko = (uint32_t)(ks * 32);
            uint32_t a0[4][4], b0[2][4];
#pragma unroll
            for (int mi = 0; mi < 4; mi++)
                ldsm4(a0[mi], sb + STG_A + aOff + mi * 1280 + ko);
#pragma unroll
            for (int nj = 0; nj < 2; nj++)
                ldsm4(b0[nj], sb + STG_B + bOff + nj * 1280 + ko);
#pragma unroll
            for (int mi = 0; mi < 4; mi++)
#pragma unroll
                for (int ni = 0; ni < 4; ni++)
                    mma16816(acc[mi][ni], a0[mi], &b0[ni >> 1][(ni & 1) * 2]);

            uint32_t b1[2][4];
#pragma unroll
            for (int nj = 0; nj < 2; nj++)
                ldsm4(b1[nj], sb + STG_BL + bOff + nj * 1280 + ko);
#pragma unroll
            for (int mi = 0; mi < 4; mi++)
#pragma unroll
                for (int ni = 0; ni < 4; ni++)
                    mma16816(acc[mi][ni], a0[mi], &b1[ni >> 1][(ni & 1) * 2]);

            uint32_t a1[4][4];
#pragma unroll
            for (int mi = 0; mi < 4; mi++)
                ldsm4(a1[mi], sb + STG_AL + aOff + mi * 1280 + ko);
#pragma unroll
            for (int mi = 0; mi < 4; mi++)
#pragma unroll
                for (int ni = 0; ni < 4; ni++)
                    mma16816(acc[mi][ni], a1[mi], &b0[ni >> 1][(ni & 1) * 2]);
        }

        if (c + 1 < nch) {
            gemm_store_chunk(smem + ((c + 1) & 1) * STG_BYTES, rg, tid);
            __syncthreads();
        }
    }

    // epilogue: direct fragment writes + bias
    const int rbase = bm + wm * 64 + (lane >> 2);
    const int cbase = bn + wn * 32 + (lane & 3) * 2;
#pragma unroll
    for (int mi = 0; mi < 4; mi++) {
#pragma unroll
        for (int ni = 0; ni < 4; ni++) {
            const int col = cbase + ni * 8;
            const float2 bv = *(const float2*)(bias + col);
            const int r0 = rbase + mi * 16;
            float2 o0, o1;
            o0.x = acc[mi][ni][0] + bv.x; o0.y = acc[mi][ni][1] + bv.y;
            o1.x = acc[mi][ni][2] + bv.x; o1.y = acc[mi][ni][3] + bv.y;
            *(float2*)(C + (size_t)r0 * N + col) = o0;
            *(float2*)(C + (size_t)(r0 + 8) * N + col) = o1;
        }
    }
}

// ================= RoPE + head split =================
__global__ void rope_split_kernel(const float* __restrict__ qkv)
{
    const int idx = blockIdx.x * blockDim.x + threadIdx.x;
    const int i = idx & 63;
    const int s = (idx >> 6) & 2047;
    const int h = (idx >> 17) & 15;
    const int b = idx >> 21;

    const size_t row = (size_t)(b * 2048 + s) * 6144;
    const int c = h * 128 + 2 * i;

    const float theta = 1.0f / powf(10000.0f, (float)(2 * i) / 128.0f);
    float sn, cs;
    sincosf((float)s * theta, &sn, &cs);

    const float q0 = qkv[row + c],        q1 = qkv[row + c + 1];
    const float k0 = qkv[row + 2048 + c], k1 = qkv[row + 2048 + c + 1];
    const float v0 = qkv[row + 4096 + c], v1 = qkv[row + 4096 + c + 1];

    const size_t ob = ((size_t)(b * 16 + h) * 2048 + s) * 128;
    g_q[ob + i]      = q0 * cs - q1 * sn;
    g_q[ob + 64 + i] = q0 * sn + q1 * cs;
    g_k[ob + i]      = k0 * cs - k1 * sn;
    g_k[ob + 64 + i] = k0 * sn + k1 * cs;
    g_v[ob + 2 * i]     = v0;
    g_v[ob + 2 * i + 1] = v1;
}

// ================= Flash attention (fp32, swizzled Q, 2 keys/iter) =================
#define ATTN_SMEM_BYTES ((128 * 32 + 2 * 32 * 32) * 16)

__global__ __launch_bounds__(128, 2) void attn_kernel()
{
    extern __shared__ float4 smem4[];
    float4* sq4 = smem4;             // 4096
    float4* sk4 = smem4 + 4096;      // 1024
    float4* sv4 = smem4 + 5120;      // 1024

    const int tid = threadIdx.x;
    const int bh = blockIdx.y;
    const int qb = blockIdx.x;

    const float4* Qp = (const float4*)(g_q + (size_t)bh * 2048 * 128 + (size_t)qb * 128 * 128);
    const float4* Kp = (const float4*)(g_k + (size_t)bh * 2048 * 128);
    const float4* Vp = (const float4*)(g_v + (size_t)bh * 2048 * 128);

    for (int it = tid; it < 4096; it += 128) {
        const int r = it >> 5, d4 = it & 31;
        sq4[r * 32 + (d4 ^ (r & 31))] = Qp[it];
    }

    float acc[128];
#pragma unroll
    for (int d = 0; d < 128; d++) acc[d] = 0.0f;
    float m = -1e30f, l = 0.0f;
    const float scale = 0.08838834764831845f;
    const int qbase = tid * 32;
    const int sw = tid & 31;

    for (int kc = 0; kc < 2048; kc += 32) {
        __syncthreads();
        for (int it = tid; it < 2048; it += 128) {
            if (it < 1024) sk4[it] = Kp[kc * 32 + it];
            else           sv4[it - 1024] = Vp[kc * 32 + it - 1024];
        }
        __syncthreads();

        for (int j = 0; j < 32; j += 2) {
            float a0 = 0.f, a1 = 0.f, a2 = 0.f, a3 = 0.f;
            float b0 = 0.f, b1 = 0.f, b2 = 0.f, b3 = 0.f;
            const float4* k0p = sk4 + j * 32;
            const float4* k1p = k0p + 32;
#pragma unroll
            for (int d4 = 0; d4 < 32; d4++) {
                const float4 qq = sq4[qbase + (d4 ^ sw)];
                const float4 k0 = k0p[d4];
                const float4 k1 = k1p[d4];
                a0 = fmaf(qq.x, k0.x, a0); a1 = fmaf(qq.y, k0.y, a1);
                a2 = fmaf(qq.z, k0.z, a2); a3 = fmaf(qq.w, k0.w, a3);
                b0 = fmaf(qq.x, k1.x, b0); b1 = fmaf(qq.y, k1.y, b1);
                b2 = fmaf(qq.z, k1.z, b2); b3 = fmaf(qq.w, k1.w, b3);
            }
            const float sc0 = (a0 + a1 + a2 + a3) * scale;
            const float sc1 = (b0 + b1 + b2 + b3) * scale;
            const float mn = fmaxf(m, fmaxf(sc0, sc1));
            if (mn > m) {
                const float alpha = __expf(m - mn);
                l *= alpha;
#pragma unroll
                for (int d = 0; d < 128; d++) acc[d] *= alpha;
                m = mn;
            }
            const float p0 = __expf(sc0 - m);
            const float p1 = __expf(sc1 - m);
            l += p0 + p1;
            const float4* v0p = sv4 + j * 32;
            const float4* v1p = v0p + 32;
#pragma unroll
            for (int d4 = 0; d4 < 32; d4++) {
                const float4 v0 = v0p[d4];
                const float4 v1 = v1p[d4];
                acc[d4 * 4 + 0] = fmaf(p0, v0.x, fmaf(p1, v1.x, acc[d4 * 4 + 0]));
                acc[d4 * 4 + 1] = fmaf(p0, v0.y, fmaf(p1, v1.y, acc[d4 * 4 + 1]));
                acc[d4 * 4 + 2] = fmaf(p0, v0.z, fmaf(p1, v1.z, acc[d4 * 4 + 2]));
                acc[d4 * 4 + 3] = fmaf(p0, v0.w, fmaf(p1, v1.w, acc[d4 * 4 + 3]));
            }
        }
    }

    const float inv_l = 1.0f / l;
    const int b = bh >> 4;
    const int h = bh & 15;
    const int srow = qb * 128 + tid;
    const size_t obase = (size_t)(b * 2048 + srow) * 2048 + h * 128;
#pragma unroll
    for (int d = 0; d < 128; d++) {
        const float o = acc[d] * inv_l;
        const __nv_bfloat16 hi = __float2bfloat16(o);
        g_att_hi[obase + d] = hi;
        g_att_lo[obase + d] = __float2bfloat16(o - __bfloat162float(hi));
    }
}

// ================= launch =================
extern "C" void kernel_launch(void* const* d_in, const int* in_sizes, int n_in,
                              void* d_out, int out_size)
{
    const float* x    = (const float*)d_in[0];
    const float* Wqkv = (const float*)d_in[1];
    const float* bqkv = (const float*)d_in[2];
    const float* Wo   = (const float*)d_in[3];
    const float* bo   = (const float*)d_in[4];
    float* out = (float*)d_out;

    float *qkv;
    __nv_bfloat16 *xh, *xl, *ah, *al, *wqh, *wql, *woh, *wol;
    cudaGetSymbolAddress((void**)&qkv, g_qkv);
    cudaGetSymbolAddress((void**)&xh, g_x_hi);
    cudaGetSymbolAddress((void**)&xl, g_x_lo);
    cudaGetSymbolAddress((void**)&ah, g_att_hi);
    cudaGetSymbolAddress((void**)&al, g_att_lo);
    cudaGetSymbolAddress((void**)&wqh, g_WqkvT_hi);
    cudaGetSymbolAddress((void**)&wql, g_WqkvT_lo);
    cudaGetSymbolAddress((void**)&woh, g_WoT_hi);
    cudaGetSymbolAddress((void**)&wol, g_WoT_lo);

    cudaFuncSetAttribute(gemm_tc, cudaFuncAttributeMaxDynamicSharedMemorySize, G_SMEM);
    cudaFuncSetAttribute(attn_kernel, cudaFuncAttributeMaxDynamicSharedMemorySize, ATTN_SMEM_BYTES);

    // prep: split x; transpose+split weights
    split_convert<<<(4096 * 2048) / 256, 256>>>(x, xh, xl, 4096 * 2048);
    transpose_split<<<dim3(6144 / 32, 2048 / 32), dim3(32, 8)>>>(Wqkv, wqh, wql, 2048, 6144);
    transpose_split<<<dim3(2048 / 32, 2048 / 32), dim3(32, 8)>>>(Wo, woh, wol, 2048, 2048);

    // 1) QKV projection (tensor cores via mma.sync)
    gemm_tc<<<dim3(6144 / 128, 4096 / 128), 256, G_SMEM>>>(xh, xl, wqh, wql, bqkv, qkv, 6144, 2048);

    // 2) RoPE + head split
    rope_split_kernel<<<(2 * 16 * 2048 * 64) / 256, 256>>>(qkv);

    // 3) Flash attention
    attn_kernel<<<dim3(2048 / 128, 2 * 16), 128, ATTN_SMEM_BYTES>>>();

    // 4) Output projection
    gemm_tc<<<dim3(2048 / 128, 4096 / 128), 256, G_SMEM>>>(ah, al, woh, wol, bo, out, 2048, 2048);
}

// round 6
// speedup vs baseline: 4.5793x; 2.9418x over previous
#include <cuda_runtime.h>
#include <cuda_bf16.h>
#include <cstdint>
#include <math.h>

// ================= scratch =================
__device__ float g_qkv[4096 * 6144];
__device__ __nv_bfloat16 g_x_hi[4096 * 2048];
__device__ __nv_bfloat16 g_x_lo[4096 * 2048];
__device__ __nv_bfloat16 g_att_hi[4096 * 2048];
__device__ __nv_bfloat16 g_att_lo[4096 * 2048];
__device__ __nv_bfloat16 g_WqkvT_hi[6144 * 2048];
__device__ __nv_bfloat16 g_WqkvT_lo[6144 * 2048];
__device__ __nv_bfloat16 g_WoT_hi[2048 * 2048];
__device__ __nv_bfloat16 g_WoT_lo[2048 * 2048];
// head-major [b*h, s, 128] bf16 hi/lo (Q has 1/sqrt(d) folded in)
__device__ __nv_bfloat16 g_qh[4096 * 2048];
__device__ __nv_bfloat16 g_ql[4096 * 2048];
__device__ __nv_bfloat16 g_kh[4096 * 2048];
__device__ __nv_bfloat16 g_kl[4096 * 2048];
// V transposed per head: [b*h, dim=128, s=2048] bf16 hi/lo
__device__ __nv_bfloat16 g_vth[4096 * 2048];
__device__ __nv_bfloat16 g_vtl[4096 * 2048];

// ================= helpers =================
__device__ __forceinline__ uint32_t smem_u32(const void* p) {
    uint32_t a;
    asm("{ .reg .u64 t; cvta.to.shared.u64 t, %1; cvt.u32.u64 %0, t; }" : "=r"(a) : "l"(p));
    return a;
}
__device__ __forceinline__ void ldsm4(uint32_t (&r)[4], uint32_t addr) {
    asm volatile("ldmatrix.sync.aligned.m8n8.x4.shared.b16 {%0,%1,%2,%3}, [%4];"
        : "=r"(r[0]), "=r"(r[1]), "=r"(r[2]), "=r"(r[3]) : "r"(addr));
}
__device__ __forceinline__ void mma16816(float* c, const uint32_t* a, const uint32_t* b) {
    asm volatile("mma.sync.aligned.m16n8k16.row.col.f32.bf16.bf16.f32 "
        "{%0,%1,%2,%3}, {%4,%5,%6,%7}, {%8,%9}, {%0,%1,%2,%3};"
        : "+f"(c[0]), "+f"(c[1]), "+f"(c[2]), "+f"(c[3])
        : "r"(a[0]), "r"(a[1]), "r"(a[2]), "r"(a[3]), "r"(b[0]), "r"(b[1]));
}
__device__ __forceinline__ uint32_t bf2_bits(__nv_bfloat162 v) {
    return *reinterpret_cast<uint32_t*>(&v);
}

// ================= prep kernels =================
__global__ void split_convert(const float* __restrict__ in,
                              __nv_bfloat16* __restrict__ hi, __nv_bfloat16* __restrict__ lo, int n) {
    int i = blockIdx.x * blockDim.x + threadIdx.x;
    if (i >= n) return;
    float v = in[i];
    __nv_bfloat16 h = __float2bfloat16(v);
    hi[i] = h;
    lo[i] = __float2bfloat16(v - __bfloat162float(h));
}

__global__ void transpose_split(const float* __restrict__ W,
                                __nv_bfloat16* __restrict__ Thi, __nv_bfloat16* __restrict__ Tlo,
                                int K, int N) {
    __shared__ float s[32][33];
    int n0 = blockIdx.x * 32, k0 = blockIdx.y * 32;
    int tx = threadIdx.x, ty = threadIdx.y;
#pragma unroll
    for (int j = 0; j < 32; j += 8)
        s[ty + j][tx] = W[(size_t)(k0 + ty + j) * N + n0 + tx];
    __syncthreads();
#pragma unroll
    for (int j = 0; j < 32; j += 8) {
        float v = s[tx][ty + j];
        __nv_bfloat16 h = __float2bfloat16(v);
        size_t o = (size_t)(n0 + ty + j) * K + k0 + tx;
        Thi[o] = h;
        Tlo[o] = __float2bfloat16(v - __bfloat162float(h));
    }
}

// ================= tensor-core GEMM via mma.sync (proven in R3) =================
#define STG_A   0
#define STG_AL  10240
#define STG_B   20480
#define STG_BL  30720
#define STG_BYTES 40960
#define G_SMEM (2 * STG_BYTES)

__device__ __forceinline__ void gemm_load_chunk(
    uint4* rg,
    const __nv_bfloat16* __restrict__ Ah, const __nv_bfloat16* __restrict__ Al,
    const __nv_bfloat16* __restrict__ Bh, const __nv_bfloat16* __restrict__ Bl,
    int bm, int bn, int K, int kc, int tid)
{
    const int i0 = tid, i1 = tid + 256;
    const int r0 = i0 >> 2, c0 = (i0 & 3) * 8;
    const int r1 = i1 >> 2, c1 = (i1 & 3) * 8;
    rg[0] = *(const uint4*)(Ah + (size_t)(bm + r0) * K + kc + c0);
    rg[1] = *(const uint4*)(Ah + (size_t)(bm + r1) * K + kc + c1);
    rg[2] = *(const uint4*)(Al + (size_t)(bm + r0) * K + kc + c0);
    rg[3] = *(const uint4*)(Al + (size_t)(bm + r1) * K + kc + c1);
    rg[4] = *(const uint4*)(Bh + (size_t)(bn + r0) * K + kc + c0);
    rg[5] = *(const uint4*)(Bh + (size_t)(bn + r1) * K + kc + c1);
    rg[6] = *(const uint4*)(Bl + (size_t)(bn + r0) * K + kc + c0);
    rg[7] = *(const uint4*)(Bl + (size_t)(bn + r1) * K + kc + c1);
}

__device__ __forceinline__ void gemm_store_chunk(char* stage, const uint4* rg, int tid)
{
    const int i0 = tid, i1 = tid + 256;
    const int o0 = (i0 >> 2) * 80 + (i0 & 3) * 16;
    const int o1 = (i1 >> 2) * 80 + (i1 & 3) * 16;
    *(uint4*)(stage + STG_A  + o0) = rg[0];
    *(uint4*)(stage + STG_A  + o1) = rg[1];
    *(uint4*)(stage + STG_AL + o0) = rg[2];
    *(uint4*)(stage + STG_AL + o1) = rg[3];
    *(uint4*)(stage + STG_B  + o0) = rg[4];
    *(uint4*)(stage + STG_B  + o1) = rg[5];
    *(uint4*)(stage + STG_BL + o0) = rg[6];
    *(uint4*)(stage + STG_BL + o1) = rg[7];
}

__global__ __launch_bounds__(256) void gemm_tc(
    const __nv_bfloat16* __restrict__ Ah, const __nv_bfloat16* __restrict__ Al,
    const __nv_bfloat16* __restrict__ Bh, const __nv_bfloat16* __restrict__ Bl,
    const float* __restrict__ bias, float* __restrict__ C, int N, int K)
{
    extern __shared__ char smem[];
    const int tid = threadIdx.x;
    const int lane = tid & 31;
    const int wid = tid >> 5;
    const int wm = wid & 1;
    const int wn = wid >> 1;
    const int bm = blockIdx.y * 128;
    const int bn = blockIdx.x * 128;

    float acc[4][4][4];
#pragma unroll
    for (int i = 0; i < 4; i++)
#pragma unroll
        for (int j = 0; j < 4; j++)
#pragma unroll
            for (int k = 0; k < 4; k++) acc[i][j][k] = 0.0f;

    const uint32_t sb0 = smem_u32(smem);
    const uint32_t aOff = (uint32_t)((wm * 64 + (lane & 15)) * 80 + ((lane >> 4) << 4));
    const uint32_t bOff = (uint32_t)((wn * 32 + (lane & 7) + ((lane >> 4) << 3)) * 80
                                     + (((lane >> 3) & 1) << 4));

    const int nch = K / 32;
    uint4 rg[8];
    gemm_load_chunk(rg, Ah, Al, Bh, Bl, bm, bn, K, 0, tid);
    gemm_store_chunk(smem, rg, tid);
    __syncthreads();

    for (int c = 0; c < nch; c++) {
        if (c + 1 < nch)
            gemm_load_chunk(rg, Ah, Al, Bh, Bl, bm, bn, K, (c + 1) * 32, tid);

        const uint32_t sb = sb0 + (uint32_t)((c & 1) * STG_BYTES);
#pragma unroll
        for (int ks = 0; ks < 2; ks++) {
            const uint32_t ko = (uint32_t)(ks * 32);
            uint32_t a0[4][4], b0[2][4];
#pragma unroll
            for (int mi = 0; mi < 4; mi++)
                ldsm4(a0[mi], sb + STG_A + aOff + mi * 1280 + ko);
#pragma unroll
            for (int nj = 0; nj < 2; nj++)
                ldsm4(b0[nj], sb + STG_B + bOff + nj * 1280 + ko);
#pragma unroll
            for (int mi = 0; mi < 4; mi++)
#pragma unroll
                for (int ni = 0; ni < 4; ni++)
                    mma16816(acc[mi][ni], a0[mi], &b0[ni >> 1][(ni & 1) * 2]);

            uint32_t b1[2][4];
#pragma unroll
            for (int nj = 0; nj < 2; nj++)
                ldsm4(b1[nj], sb + STG_BL + bOff + nj * 1280 + ko);
#pragma unroll
            for (int mi = 0; mi < 4; mi++)
#pragma unroll
                for (int ni = 0; ni < 4; ni++)
                    mma16816(acc[mi][ni], a0[mi], &b1[ni >> 1][(ni & 1) * 2]);

            uint32_t a1[4][4];
#pragma unroll
            for (int mi = 0; mi < 4; mi++)
                ldsm4(a1[mi], sb + STG_AL + aOff + mi * 1280 + ko);
#pragma unroll
            for (int mi = 0; mi < 4; mi++)
#pragma unroll
                for (int ni = 0; ni < 4; ni++)
                    mma16816(acc[mi][ni], a1[mi], &b0[ni >> 1][(ni & 1) * 2]);
        }

        if (c + 1 < nch) {
            gemm_store_chunk(smem + ((c + 1) & 1) * STG_BYTES, rg, tid);
            __syncthreads();
        }
    }

    const int rbase = bm + wm * 64 + (lane >> 2);
    const int cbase = bn + wn * 32 + (lane & 3) * 2;
#pragma unroll
    for (int mi = 0; mi < 4; mi++) {
#pragma unroll
        for (int ni = 0; ni < 4; ni++) {
            const int col = cbase + ni * 8;
            const float2 bv = *(const float2*)(bias + col);
            const int r0 = rbase + mi * 16;
            float2 o0, o1;
            o0.x = acc[mi][ni][0] + bv.x; o0.y = acc[mi][ni][1] + bv.y;
            o1.x = acc[mi][ni][2] + bv.x; o1.y = acc[mi][ni][3] + bv.y;
            *(float2*)(C + (size_t)r0 * N + col) = o0;
            *(float2*)(C + (size_t)(r0 + 8) * N + col) = o1;
        }
    }
}

// ================= RoPE + head split -> bf16 hi/lo (V transposed) =================
__device__ __forceinline__ void split_store(__nv_bfloat16* H, __nv_bfloat16* L,
                                            size_t o, float v) {
    __nv_bfloat16 h = __float2bfloat16(v);
    H[o] = h;
    L[o] = __float2bfloat16(v - __bfloat162float(h));
}

__global__ void rope_split_kernel(const float* __restrict__ qkv)
{
    const int idx = blockIdx.x * blockDim.x + threadIdx.x;
    const int i = idx & 63;
    const int s = (idx >> 6) & 2047;
    const int h = (idx >> 17) & 15;
    const int b = idx >> 21;

    const size_t row = (size_t)(b * 2048 + s) * 6144;
    const int c = h * 128 + 2 * i;

    const float theta = 1.0f / powf(10000.0f, (float)(2 * i) / 128.0f);
    float sn, cs;
    sincosf((float)s * theta, &sn, &cs);

    const float q0 = qkv[row + c],        q1 = qkv[row + c + 1];
    const float k0 = qkv[row + 2048 + c], k1 = qkv[row + 2048 + c + 1];
    const float v0 = qkv[row + 4096 + c], v1 = qkv[row + 4096 + c + 1];

    const float scale = 0.08838834764831845f; // 1/sqrt(128), folded into Q
    const int bh = b * 16 + h;
    const size_t ob = ((size_t)bh * 2048 + s) * 128;

    split_store(g_qh, g_ql, ob + i,      (q0 * cs - q1 * sn) * scale);
    split_store(g_qh, g_ql, ob + 64 + i, (q0 * sn + q1 * cs) * scale);
    split_store(g_kh, g_kl, ob + i,      k0 * cs - k1 * sn);
    split_store(g_kh, g_kl, ob + 64 + i, k0 * sn + k1 * cs);
    // V transposed: [bh][dim][s]
    const size_t vt = ((size_t)bh * 128 + 2 * i) * 2048 + s;
    split_store(g_vth, g_vtl, vt, v0);
    split_store(g_vth, g_vtl, vt + 2048, v1);
}

// ================= tensor-core flash attention =================
// CTA: 128 queries (8 warps x 16 rows), 64-key chunks.
// Q/K rows: 128 bf16 @ 272B stride. V^T rows: 64 keys @ 144B stride. P: 64 cols @ 144B.
#define AT_ROW   272
#define AT_VROW  144
#define AT_SQ_H  0
#define AT_SQ_L  34816
#define AT_SK_H  69632
#define AT_SK_L  87040
#define AT_VT_H  104448
#define AT_VT_L  122880
#define AT_P_H   141312
#define AT_P_L   159744
#define AT_SMEM  178176

__global__ __launch_bounds__(256) void attn_tc()
{
    extern __shared__ char sm[];
    const uint32_t sb = smem_u32(sm);
    const int tid = threadIdx.x;
    const int lane = tid & 31;
    const int w = tid >> 5;
    const int qb = blockIdx.x;
    const int bh = blockIdx.y;

    const size_t hbase = (size_t)bh * 2048 * 128;
    const uint4* Qh = (const uint4*)(g_qh + hbase + (size_t)qb * 128 * 128);
    const uint4* Ql = (const uint4*)(g_ql + hbase + (size_t)qb * 128 * 128);
    const uint4* Kh = (const uint4*)(g_kh + hbase);
    const uint4* Kl = (const uint4*)(g_kl + hbase);

    // load Q tile: 128 rows x 16 uint4 = 2048 uint4 (hi+lo)   [R5 bug: was 1024]
    for (int i = tid; i < 2048; i += 256) {
        const uint32_t off = (uint32_t)((i >> 4) * AT_ROW + (i & 15) * 16);
        *(uint4*)(sm + AT_SQ_H + off) = Qh[i];
        *(uint4*)(sm + AT_SQ_L + off) = Ql[i];
    }

    // fragment address bases (proven gemm patterns)
    const uint32_t aOff = (uint32_t)((w * 16 + (lane & 15)) * AT_ROW + ((lane >> 4) << 4));
    const uint32_t bOff = (uint32_t)(((lane & 7) + ((lane >> 4) << 3)) * AT_ROW
                                     + (((lane >> 3) & 1) << 4));
    const uint32_t bV   = (uint32_t)(((lane & 7) + ((lane >> 4) << 3)) * AT_VROW
                                     + (((lane >> 3) & 1) << 4));
    const uint32_t aP   = (uint32_t)((lane & 15) * AT_VROW + ((lane >> 4) << 4));
    const uint32_t pwH  = sb + AT_P_H + (uint32_t)(w * 16 * AT_VROW);
    const uint32_t pwL  = sb + AT_P_L + (uint32_t)(w * 16 * AT_VROW);

    float O[16][4];
#pragma unroll
    for (int i = 0; i < 16; i++)
#pragma unroll
        for (int j = 0; j < 4; j++) O[i][j] = 0.0f;
    float m0 = -30000.0f, m1 = -30000.0f, l0 = 0.0f, l1 = 0.0f;

    const int g = lane >> 2, lam = lane & 3;

    for (int kc = 0; kc < 2048; kc += 64) {
        __syncthreads();
        for (int i = tid; i < 1024; i += 256) {
            // K chunk: 64 rows x 16 uint4
            const uint32_t offK = (uint32_t)((i >> 4) * AT_ROW + (i & 15) * 16);
            const int giK = kc * 16 + i;
            *(uint4*)(sm + AT_SK_H + offK) = Kh[giK];
            *(uint4*)(sm + AT_SK_L + offK) = Kl[giK];
            // V^T chunk: 128 dim-rows x 8 uint4 (64 keys)
            const int vr = i >> 3;
            const uint32_t offV = (uint32_t)(vr * AT_VROW + (i & 7) * 16);
            const uint4* vhp = (const uint4*)(g_vth + ((size_t)bh * 128 + vr) * 2048 + kc);
            const uint4* vlp = (const uint4*)(g_vtl + ((size_t)bh * 128 + vr) * 2048 + kc);
            *(uint4*)(sm + AT_VT_H + offV) = vhp[i & 7];
            *(uint4*)(sm + AT_VT_L + offV) = vlp[i & 7];
        }
        __syncthreads();

        // ---- S = Q @ K^T (3-term split) ----
        float S[8][4];
#pragma unroll
        for (int t = 0; t < 8; t++)
#pragma unroll
            for (int j = 0; j < 4; j++) S[t][j] = 0.0f;

#pragma unroll
        for (int kk = 0; kk < 8; kk++) {
            uint32_t ah[4], al[4];
            ldsm4(ah, sb + AT_SQ_H + aOff + kk * 32);
            ldsm4(al, sb + AT_SQ_L + aOff + kk * 32);
#pragma unroll
            for (int kg = 0; kg < 4; kg++) {
                uint32_t kbh[4], kbl[4];
                ldsm4(kbh, sb + AT_SK_H + bOff + kg * (16 * AT_ROW) + kk * 32);
                ldsm4(kbl, sb + AT_SK_L + bOff + kg * (16 * AT_ROW) + kk * 32);
                mma16816(S[2 * kg],     ah, kbh + 0);
                mma16816(S[2 * kg + 1], ah, kbh + 2);
                mma16816(S[2 * kg],     ah, kbl + 0);
                mma16816(S[2 * kg + 1], ah, kbl + 2);
                mma16816(S[2 * kg],     al, kbh + 0);
                mma16816(S[2 * kg + 1], al, kbh + 2);
            }
        }

        // ---- online softmax ----
        float mx0 = -30000.0f, mx1 = -30000.0f;
#pragma unroll
        for (int t = 0; t < 8; t++) {
            mx0 = fmaxf(mx0, fmaxf(S[t][0], S[t][1]));
            mx1 = fmaxf(mx1, fmaxf(S[t][2], S[t][3]));
        }
        mx0 = fmaxf(mx0, __shfl_xor_sync(0xffffffff, mx0, 1));
        mx0 = fmaxf(mx0, __shfl_xor_sync(0xffffffff, mx0, 2));
        mx1 = fmaxf(mx1, __shfl_xor_sync(0xffffffff, mx1, 1));
        mx1 = fmaxf(mx1, __shfl_xor_sync(0xffffffff, mx1, 2));

        const float nm0 = fmaxf(m0, mx0);
        const float nm1 = fmaxf(m1, mx1);
        const float al0 = __expf(fminf(m0 - nm0, 0.0f));
        const float al1 = __expf(fminf(m1 - nm1, 0.0f));
        m0 = nm0; m1 = nm1;

        float s0 = 0.0f, s1 = 0.0f;
#pragma unroll
        for (int t = 0; t < 8; t++) {
            S[t][0] = __expf(fminf(S[t][0] - m0, 0.0f));
            S[t][1] = __expf(fminf(S[t][1] - m0, 0.0f));
            S[t][2] = __expf(fminf(S[t][2] - m1, 0.0f));
            S[t][3] = __expf(fminf(S[t][3] - m1, 0.0f));
            s0 += S[t][0] + S[t][1];
            s1 += S[t][2] + S[t][3];
        }
        l0 = l0 * al0 + s0;
        l1 = l1 * al1 + s1;
#pragma unroll
        for (int nt = 0; nt < 16; nt++) {
            O[nt][0] *= al0; O[nt][1] *= al0;
            O[nt][2] *= al1; O[nt][3] *= al1;
        }

        // ---- write P (bf16 hi/lo) to warp-private smem (accumulator layout) ----
#pragma unroll
        for (int t = 0; t < 8; t++) {
            const uint32_t cb = (uint32_t)(t * 16 + lam * 4);
            __nv_bfloat162 h0 = __floats2bfloat162_rn(S[t][0], S[t][1]);
            __nv_bfloat162 r0 = __floats2bfloat162_rn(S[t][0] - __bfloat162float(h0.x),
                                                      S[t][1] - __bfloat162float(h0.y));
            __nv_bfloat162 h1 = __floats2bfloat162_rn(S[t][2], S[t][3]);
            __nv_bfloat162 r1 = __floats2bfloat162_rn(S[t][2] - __bfloat162float(h1.x),
                                                      S[t][3] - __bfloat162float(h1.y));
            *(uint32_t*)(sm + (pwH - sb) + g * AT_VROW + cb)       = bf2_bits(h0);
            *(uint32_t*)(sm + (pwL - sb) + g * AT_VROW + cb)       = bf2_bits(r0);
            *(uint32_t*)(sm + (pwH - sb) + (g + 8) * AT_VROW + cb) = bf2_bits(h1);
            *(uint32_t*)(sm + (pwL - sb) + (g + 8) * AT_VROW + cb) = bf2_bits(r1);
        }
        __syncwarp();

        // ---- O += P @ V (3-term split) ----
#pragma unroll
        for (int kt = 0; kt < 4; kt++) {
            uint32_t ph[4], pl[4];
            ldsm4(ph, pwH + aP + kt * 32);
            ldsm4(pl, pwL + aP + kt * 32);
#pragma unroll
            for (int j = 0; j < 8; j++) {
                uint32_t vbh[4], vbl[4];
                ldsm4(vbh, sb + AT_VT_H + bV + j * (16 * AT_VROW) + kt * 32);
                ldsm4(vbl, sb + AT_VT_L + bV + j * (16 * AT_VROW) + kt * 32);
                mma16816(O[2 * j],     ph, vbh + 0);
                mma16816(O[2 * j + 1], ph, vbh + 2);
                mma16816(O[2 * j],     ph, vbl + 0);
                mma16816(O[2 * j + 1], ph, vbl + 2);
                mma16816(O[2 * j],     pl, vbh + 0);
                mma16816(O[2 * j + 1], pl, vbh + 2);
            }
        }
        __syncwarp();
    }

    // ---- epilogue ----
    l0 += __shfl_xor_sync(0xffffffff, l0, 1);
    l0 += __shfl_xor_sync(0xffffffff, l0, 2);
    l1 += __shfl_xor_sync(0xffffffff, l1, 1);
    l1 += __shfl_xor_sync(0xffffffff, l1, 2);
    const float inv0 = 1.0f / l0;
    const float inv1 = 1.0f / l1;

    const int bb = bh >> 4, hh2 = bh & 15;
    const int row0 = qb * 128 + w * 16 + g;
    const size_t base0 = (size_t)(bb * 2048 + row0) * 2048 + hh2 * 128 + lam * 2;
    const size_t base1 = base0 + (size_t)8 * 2048;

#pragma unroll
    for (int nt = 0; nt < 16; nt++) {
        float x0 = O[nt][0] * inv0, x1 = O[nt][1] * inv0;
        __nv_bfloat162 hx = __floats2bfloat162_rn(x0, x1);
        __nv_bfloat162 lx = __floats2bfloat162_rn(x0 - __bfloat162float(hx.x),
                                                  x1 - __bfloat162float(hx.y));
        *(uint32_t*)(g_att_hi + base0 + nt * 8) = bf2_bits(hx);
        *(uint32_t*)(g_att_lo + base0 + nt * 8) = bf2_bits(lx);

        float x2 = O[nt][2] * inv1, x3 = O[nt][3] * inv1;
        hx = __floats2bfloat162_rn(x2, x3);
        lx = __floats2bfloat162_rn(x2 - __bfloat162float(hx.x),
                                   x3 - __bfloat162float(hx.y));
        *(uint32_t*)(g_att_hi + base1 + nt * 8) = bf2_bits(hx);
        *(uint32_t*)(g_att_lo + base1 + nt * 8) = bf2_bits(lx);
    }
}

// ================= launch =================
extern "C" void kernel_launch(void* const* d_in, const int* in_sizes, int n_in,
                              void* d_out, int out_size)
{
    const float* x    = (const float*)d_in[0];
    const float* Wqkv = (const float*)d_in[1];
    const float* bqkv = (const float*)d_in[2];
    const float* Wo   = (const float*)d_in[3];
    const float* bo   = (const float*)d_in[4];
    float* out = (float*)d_out;

    float *qkv;
    __nv_bfloat16 *xh, *xl, *ah, *al, *wqh, *wql, *woh, *wol;
    cudaGetSymbolAddress((void**)&qkv, g_qkv);
    cudaGetSymbolAddress((void**)&xh, g_x_hi);
    cudaGetSymbolAddress((void**)&xl, g_x_lo);
    cudaGetSymbolAddress((void**)&ah, g_att_hi);
    cudaGetSymbolAddress((void**)&al, g_att_lo);
    cudaGetSymbolAddress((void**)&wqh, g_WqkvT_hi);
    cudaGetSymbolAddress((void**)&wql, g_WqkvT_lo);
    cudaGetSymbolAddress((void**)&woh, g_WoT_hi);
    cudaGetSymbolAddress((void**)&wol, g_WoT_lo);

    cudaFuncSetAttribute(gemm_tc, cudaFuncAttributeMaxDynamicSharedMemorySize, G_SMEM);
    cudaFuncSetAttribute(attn_tc, cudaFuncAttributeMaxDynamicSharedMemorySize, AT_SMEM);

    // prep
    split_convert<<<(4096 * 2048) / 256, 256>>>(x, xh, xl, 4096 * 2048);
    transpose_split<<<dim3(6144 / 32, 2048 / 32), dim3(32, 8)>>>(Wqkv, wqh, wql, 2048, 6144);
    transpose_split<<<dim3(2048 / 32, 2048 / 32), dim3(32, 8)>>>(Wo, woh, wol, 2048, 2048);

    // 1) QKV projection
    gemm_tc<<<dim3(6144 / 128, 4096 / 128), 256, G_SMEM>>>(xh, xl, wqh, wql, bqkv, qkv, 6144, 2048);

    // 2) RoPE + head split (bf16 hi/lo; V transposed per head)
    rope_split_kernel<<<(2 * 16 * 2048 * 64) / 256, 256>>>(qkv);

    // 3) Tensor-core flash attention
    attn_tc<<<dim3(2048 / 128, 2 * 16), 256, AT_SMEM>>>();

    // 4) Output projection
    gemm_tc<<<dim3(2048 / 128, 4096 / 128), 256, G_SMEM>>>(ah, al, woh, wol, bo, out, 2048, 2048);
}

// round 7
// speedup vs baseline: 4.8003x; 1.0483x over previous
#include <cuda_runtime.h>
#include <cuda_bf16.h>
#include <cstdint>
#include <math.h>

// ================= scratch =================
__device__ __nv_bfloat16 g_x_hi[4096 * 2048];
__device__ __nv_bfloat16 g_x_lo[4096 * 2048];
__device__ __nv_bfloat16 g_att_hi[4096 * 2048];
__device__ __nv_bfloat16 g_att_lo[4096 * 2048];
__device__ __nv_bfloat16 g_WqkvT_hi[6144 * 2048];
__device__ __nv_bfloat16 g_WqkvT_lo[6144 * 2048];
__device__ __nv_bfloat16 g_WoT_hi[2048 * 2048];
__device__ __nv_bfloat16 g_WoT_lo[2048 * 2048];
// head-major [b*h, s, 128] bf16 hi/lo (Q has 1/sqrt(d) folded in)
__device__ __nv_bfloat16 g_qh[4096 * 2048];
__device__ __nv_bfloat16 g_ql[4096 * 2048];
__device__ __nv_bfloat16 g_kh[4096 * 2048];
__device__ __nv_bfloat16 g_kl[4096 * 2048];
// V transposed per head: [b*h, dim=128, s=2048] bf16 hi/lo
__device__ __nv_bfloat16 g_vth[4096 * 2048];
__device__ __nv_bfloat16 g_vtl[4096 * 2048];

// ================= helpers =================
__device__ __forceinline__ uint32_t smem_u32(const void* p) {
    uint32_t a;
    asm("{ .reg .u64 t; cvta.to.shared.u64 t, %1; cvt.u32.u64 %0, t; }" : "=r"(a) : "l"(p));
    return a;
}
__device__ __forceinline__ void ldsm4(uint32_t (&r)[4], uint32_t addr) {
    asm volatile("ldmatrix.sync.aligned.m8n8.x4.shared.b16 {%0,%1,%2,%3}, [%4];"
        : "=r"(r[0]), "=r"(r[1]), "=r"(r[2]), "=r"(r[3]) : "r"(addr));
}
__device__ __forceinline__ void mma16816(float* c, const uint32_t* a, const uint32_t* b) {
    asm volatile("mma.sync.aligned.m16n8k16.row.col.f32.bf16.bf16.f32 "
        "{%0,%1,%2,%3}, {%4,%5,%6,%7}, {%8,%9}, {%0,%1,%2,%3};"
        : "+f"(c[0]), "+f"(c[1]), "+f"(c[2]), "+f"(c[3])
        : "r"(a[0]), "r"(a[1]), "r"(a[2]), "r"(a[3]), "r"(b[0]), "r"(b[1]));
}
__device__ __forceinline__ uint32_t bf2_bits(__nv_bfloat162 v) {
    return *reinterpret_cast<uint32_t*>(&v);
}
__device__ __forceinline__ void stage_split(__nv_bfloat16* hi, __nv_bfloat16* lo,
                                            int off, float v) {
    __nv_bfloat16 h = __float2bfloat16(v);
    hi[off] = h;
    lo[off] = __float2bfloat16(v - __bfloat162float(h));
}

// ================= prep kernels =================
__global__ void split_convert(const float* __restrict__ in,
                              __nv_bfloat16* __restrict__ hi, __nv_bfloat16* __restrict__ lo, int n) {
    int i = blockIdx.x * blockDim.x + threadIdx.x;
    if (i >= n) return;
    float v = in[i];
    __nv_bfloat16 h = __float2bfloat16(v);
    hi[i] = h;
    lo[i] = __float2bfloat16(v - __bfloat162float(h));
}

__global__ void transpose_split(const float* __restrict__ W,
                                __nv_bfloat16* __restrict__ Thi, __nv_bfloat16* __restrict__ Tlo,
                                int K, int N) {
    __shared__ float s[32][33];
    int n0 = blockIdx.x * 32, k0 = blockIdx.y * 32;
    int tx = threadIdx.x, ty = threadIdx.y;
#pragma unroll
    for (int j = 0; j < 32; j += 8)
        s[ty + j][tx] = W[(size_t)(k0 + ty + j) * N + n0 + tx];
    __syncthreads();
#pragma unroll
    for (int j = 0; j < 32; j += 8) {
        float v = s[tx][ty + j];
        __nv_bfloat16 h = __float2bfloat16(v);
        size_t o = (size_t)(n0 + ty + j) * K + k0 + tx;
        Thi[o] = h;
        Tlo[o] = __float2bfloat16(v - __bfloat162float(h));
    }
}

// ================= shared GEMM mainloop pieces (proven R3/R6) =================
#define STG_A   0
#define STG_AL  10240
#define STG_B   20480
#define STG_BL  30720
#define STG_BYTES 40960
#define G_SMEM (2 * STG_BYTES)

__device__ __forceinline__ void gemm_load_chunk(
    uint4* rg,
    const __nv_bfloat16* __restrict__ Ah, const __nv_bfloat16* __restrict__ Al,
    const __nv_bfloat16* __restrict__ Bh, const __nv_bfloat16* __restrict__ Bl,
    int bm, int bn, int K, int kc, int tid)
{
    const int i0 = tid, i1 = tid + 256;
    const int r0 = i0 >> 2, c0 = (i0 & 3) * 8;
    const int r1 = i1 >> 2, c1 = (i1 & 3) * 8;
    rg[0] = *(const uint4*)(Ah + (size_t)(bm + r0) * K + kc + c0);
    rg[1] = *(const uint4*)(Ah + (size_t)(bm + r1) * K + kc + c1);
    rg[2] = *(const uint4*)(Al + (size_t)(bm + r0) * K + kc + c0);
    rg[3] = *(const uint4*)(Al + (size_t)(bm + r1) * K + kc + c1);
    rg[4] = *(const uint4*)(Bh + (size_t)(bn + r0) * K + kc + c0);
    rg[5] = *(const uint4*)(Bh + (size_t)(bn + r1) * K + kc + c1);
    rg[6] = *(const uint4*)(Bl + (size_t)(bn + r0) * K + kc + c0);
    rg[7] = *(const uint4*)(Bl + (size_t)(bn + r1) * K + kc + c1);
}

__device__ __forceinline__ void gemm_store_chunk(char* stage, const uint4* rg, int tid)
{
    const int i0 = tid, i1 = tid + 256;
    const int o0 = (i0 >> 2) * 80 + (i0 & 3) * 16;
    const int o1 = (i1 >> 2) * 80 + (i1 & 3) * 16;
    *(uint4*)(stage + STG_A  + o0) = rg[0];
    *(uint4*)(stage + STG_A  + o1) = rg[1];
    *(uint4*)(stage + STG_AL + o0) = rg[2];
    *(uint4*)(stage + STG_AL + o1) = rg[3];
    *(uint4*)(stage + STG_B  + o0) = rg[4];
    *(uint4*)(stage + STG_B  + o1) = rg[5];
    *(uint4*)(stage + STG_BL + o0) = rg[6];
    *(uint4*)(stage + STG_BL + o1) = rg[7];
}

// mainloop macro: computes acc[4][4][4] for tile (bm,bn)
#define GEMM_MAINLOOP(Ah, Al, Bh, Bl, K)                                            \
    float acc[4][4][4];                                                             \
    _Pragma("unroll") for (int i = 0; i < 4; i++)                                   \
    _Pragma("unroll") for (int j = 0; j < 4; j++)                                   \
    _Pragma("unroll") for (int k = 0; k < 4; k++) acc[i][j][k] = 0.0f;              \
    const uint32_t sb0 = smem_u32(smem);                                            \
    const uint32_t aOff = (uint32_t)((wm * 64 + (lane & 15)) * 80 + ((lane >> 4) << 4)); \
    const uint32_t bOff = (uint32_t)((wn * 32 + (lane & 7) + ((lane >> 4) << 3)) * 80    \
                                     + (((lane >> 3) & 1) << 4));                   \
    const int nch = (K) / 32;                                                       \
    uint4 rg[8];                                                                    \
    gemm_load_chunk(rg, Ah, Al, Bh, Bl, bm, bn, K, 0, tid);                         \
    gemm_store_chunk(smem, rg, tid);                                                \
    __syncthreads();                                                                \
    for (int c = 0; c < nch; c++) {                                                 \
        if (c + 1 < nch)                                                            \
            gemm_load_chunk(rg, Ah, Al, Bh, Bl, bm, bn, K, (c + 1) * 32, tid);      \
        const uint32_t sb = sb0 + (uint32_t)((c & 1) * STG_BYTES);                  \
        _Pragma("unroll")                                                           \
        for (int ks = 0; ks < 2; ks++) {                                            \
            const uint32_t ko = (uint32_t)(ks * 32);                                \
            uint32_t a0[4][4], b0[2][4];                                            \
            _Pragma("unroll") for (int mi = 0; mi < 4; mi++)                        \
                ldsm4(a0[mi], sb + STG_A + aOff + mi * 1280 + ko);                  \
            _Pragma("unroll") for (int nj = 0; nj < 2; nj++)                        \
                ldsm4(b0[nj], sb + STG_B + bOff + nj * 1280 + ko);                  \
            _Pragma("unroll") for (int mi = 0; mi < 4; mi++)                        \
            _Pragma("unroll") for (int ni = 0; ni < 4; ni++)                        \
                mma16816(acc[mi][ni], a0[mi], &b0[ni >> 1][(ni & 1) * 2]);          \
            uint32_t b1[2][4];                                                      \
            _Pragma("unroll") for (int nj = 0; nj < 2; nj++)                        \
                ldsm4(b1[nj], sb + STG_BL + bOff + nj * 1280 + ko);                 \
            _Pragma("unroll") for (int mi = 0; mi < 4; mi++)                        \
            _Pragma("unroll") for (int ni = 0; ni < 4; ni++)                        \
                mma16816(acc[mi][ni], a0[mi], &b1[ni >> 1][(ni & 1) * 2]);          \
            uint32_t a1[4][4];                                                      \
            _Pragma("unroll") for (int mi = 0; mi < 4; mi++)                        \
                ldsm4(a1[mi], sb + STG_AL + aOff + mi * 1280 + ko);                 \
            _Pragma("unroll") for (int mi = 0; mi < 4; mi++)                        \
            _Pragma("unroll") for (int ni = 0; ni < 4; ni++)                        \
                mma16816(acc[mi][ni], a1[mi], &b0[ni >> 1][(ni & 1) * 2]);          \
        }                                                                           \
        if (c + 1 < nch) {                                                          \
            gemm_store_chunk(smem + ((c + 1) & 1) * STG_BYTES, rg, tid);            \
            __syncthreads();                                                        \
        }                                                                           \
    }

// ================= GEMM #2: out-proj (float out + bias), unchanged =================
__global__ __launch_bounds__(256) void gemm_tc(
    const __nv_bfloat16* __restrict__ Ah, const __nv_bfloat16* __restrict__ Al,
    const __nv_bfloat16* __restrict__ Bh, const __nv_bfloat16* __restrict__ Bl,
    const float* __restrict__ bias, float* __restrict__ C, int N, int K)
{
    extern __shared__ char smem[];
    const int tid = threadIdx.x;
    const int lane = tid & 31;
    const int wid = tid >> 5;
    const int wm = wid & 1;
    const int wn = wid >> 1;
    const int bm = blockIdx.y * 128;
    const int bn = blockIdx.x * 128;

    GEMM_MAINLOOP(Ah, Al, Bh, Bl, K)

    const int rbase = bm + wm * 64 + (lane >> 2);
    const int cbase = bn + wn * 32 + (lane & 3) * 2;
#pragma unroll
    for (int mi = 0; mi < 4; mi++) {
#pragma unroll
        for (int ni = 0; ni < 4; ni++) {
            const int col = cbase + ni * 8;
            const float2 bv = *(const float2*)(bias + col);
            const int r0 = rbase + mi * 16;
            float2 o0, o1;
            o0.x = acc[mi][ni][0] + bv.x; o0.y = acc[mi][ni][1] + bv.y;
            o1.x = acc[mi][ni][2] + bv.x; o1.y = acc[mi][ni][3] + bv.y;
            *(float2*)(C + (size_t)r0 * N + col) = o0;
            *(float2*)(C + (size_t)(r0 + 8) * N + col) = o1;
        }
    }
}

// ================= GEMM #1: QKV projection with fused RoPE/split epilogue =================
// N tile (128) == one head of one segment. Emits g_q/g_k (rope'd, hi/lo) and g_vt (transposed).
__global__ __launch_bounds__(256) void gemm_qkv_rope(
    const __nv_bfloat16* __restrict__ Ah, const __nv_bfloat16* __restrict__ Al,
    const __nv_bfloat16* __restrict__ Bh, const __nv_bfloat16* __restrict__ Bl,
    const float* __restrict__ bias)
{
    extern __shared__ char smem[];
    const int tid = threadIdx.x;
    const int lane = tid & 31;
    const int wid = tid >> 5;
    const int wm = wid & 1;
    const int wn = wid >> 1;
    const int bm = blockIdx.y * 128;
    const int bn = blockIdx.x * 128;
    const int K = 2048;

    GEMM_MAINLOOP(Ah, Al, Bh, Bl, K)

    // ---------- fused epilogue ----------
    __syncthreads();  // mainloop smem reads done before staging overwrites

    const int seg   = bn >> 11;          // 0=Q 1=K 2=V
    const int head  = (bn & 2047) >> 7;
    const int bidx  = bm >> 11;
    const int s_base = bm & 2047;
    const int bhh   = bidx * 16 + head;

    __nv_bfloat16* sh_hi = (__nv_bfloat16*)smem;            // 128x128 bf16
    __nv_bfloat16* sh_lo = (__nv_bfloat16*)(smem + 32768);

    const int rl = wm * 64 + (lane >> 2);
    const int cb = wn * 32 + (lane & 3) * 2;
    const float qscale = 0.08838834764831845f;

#pragma unroll
    for (int mi = 0; mi < 4; mi++) {
#pragma unroll
        for (int ni = 0; ni < 4; ni++) {
            const int c = cb + ni * 8;
            const float b0 = bias[bn + c], b1 = bias[bn + c + 1];
            float v0 = acc[mi][ni][0] + b0, v1 = acc[mi][ni][1] + b1;
            float w0 = acc[mi][ni][2] + b0, w1 = acc[mi][ni][3] + b1;
            const int r0 = rl + mi * 16, r1 = r0 + 8;
            if (seg < 2) {
                const int j = c >> 1;
                const float theta = 1.0f / powf(10000.0f, (float)(2 * j) / 128.0f);
                float sn0, cs0, sn1, cs1;
                sincosf((float)(s_base + r0) * theta, &sn0, &cs0);
                sincosf((float)(s_base + r1) * theta, &sn1, &cs1);
                float a0 = v0 * cs0 - v1 * sn0, o0 = v0 * sn0 + v1 * cs0;
                float a1 = w0 * cs1 - w1 * sn1, o1 = w0 * sn1 + w1 * cs1;
                if (seg == 0) { a0 *= qscale; o0 *= qscale; a1 *= qscale; o1 *= qscale; }
                stage_split(sh_hi, sh_lo, r0 * 128 + j,      a0);
                stage_split(sh_hi, sh_lo, r0 * 128 + j + 64, o0);
                stage_split(sh_hi, sh_lo, r1 * 128 + j,      a1);
                stage_split(sh_hi, sh_lo, r1 * 128 + j + 64, o1);
            } else {
                // V: stage transposed [d][r]
                stage_split(sh_hi, sh_lo, c * 128 + r0,       v0);
                stage_split(sh_hi, sh_lo, (c + 1) * 128 + r0, v1);
                stage_split(sh_hi, sh_lo, c * 128 + r1,       w0);
                stage_split(sh_hi, sh_lo, (c + 1) * 128 + r1, w1);
            }
        }
    }
    __syncthreads();

    if (seg < 2) {
        __nv_bfloat16* Hd = (seg == 0) ? g_qh : g_kh;
        __nv_bfloat16* Ld = (seg == 0) ? g_ql : g_kl;
        for (int i = tid; i < 2048; i += 256) {
            const int row = i >> 4, q = i & 15;
            const size_t eo = ((size_t)bhh * 2048 + s_base + row) * 128 + q * 8;
            *(uint4*)(Hd + eo) = *(const uint4*)(sh_hi + row * 128 + q * 8);
            *(uint4*)(Ld + eo) = *(const uint4*)(sh_lo + row * 128 + q * 8);
        }
    } else {
        for (int i = tid; i < 2048; i += 256) {
            const int d = i >> 4, q = i & 15;
            const size_t eo = ((size_t)(bhh * 128 + d)) * 2048 + s_base + q * 8;
            *(uint4*)(g_vth + eo) = *(const uint4*)(sh_hi + d * 128 + q * 8);
            *(uint4*)(g_vtl + eo) = *(const uint4*)(sh_lo + d * 128 + q * 8);
        }
    }
}

// ================= tensor-core flash attention (register-prefetched K/V) =================
#define AT_ROW   272
#define AT_VROW  144
#define AT_SQ_H  0
#define AT_SQ_L  34816
#define AT_SK_H  69632
#define AT_SK_L  87040
#define AT_VT_H  104448
#define AT_VT_L  122880
#define AT_P_H   141312
#define AT_P_L   159744
#define AT_SMEM  178176

__global__ __launch_bounds__(256) void attn_tc()
{
    extern __shared__ char sm[];
    const uint32_t sb = smem_u32(sm);
    const int tid = threadIdx.x;
    const int lane = tid & 31;
    const int w = tid >> 5;
    const int qb = blockIdx.x;
    const int bh = blockIdx.y;

    const size_t hbase = (size_t)bh * 2048 * 128;
    const uint4* Qh = (const uint4*)(g_qh + hbase + (size_t)qb * 128 * 128);
    const uint4* Ql = (const uint4*)(g_ql + hbase + (size_t)qb * 128 * 128);
    const uint4* Kh = (const uint4*)(g_kh + hbase);
    const uint4* Kl = (const uint4*)(g_kl + hbase);

    // load Q tile: 128 rows x 16 uint4 (hi+lo)
    for (int i = tid; i < 2048; i += 256) {
        const uint32_t off = (uint32_t)((i >> 4) * AT_ROW + (i & 15) * 16);
        *(uint4*)(sm + AT_SQ_H + off) = Qh[i];
        *(uint4*)(sm + AT_SQ_L + off) = Ql[i];
    }

    const uint32_t aOff = (uint32_t)((w * 16 + (lane & 15)) * AT_ROW + ((lane >> 4) << 4));
    const uint32_t bOff = (uint32_t)(((lane & 7) + ((lane >> 4) << 3)) * AT_ROW
                                     + (((lane >> 3) & 1) << 4));
    const uint32_t bV   = (uint32_t)(((lane & 7) + ((lane >> 4) << 3)) * AT_VROW
                                     + (((lane >> 3) & 1) << 4));
    const uint32_t aP   = (uint32_t)((lane & 15) * AT_VROW + ((lane >> 4) << 4));
    const uint32_t pwH  = sb + AT_P_H + (uint32_t)(w * 16 * AT_VROW);
    const uint32_t pwL  = sb + AT_P_L + (uint32_t)(w * 16 * AT_VROW);

    float O[16][4];
#pragma unroll
    for (int i = 0; i < 16; i++)
#pragma unroll
        for (int j = 0; j < 4; j++) O[i][j] = 0.0f;
    float m0 = -30000.0f, m1 = -30000.0f, l0 = 0.0f, l1 = 0.0f;

    const int g = lane >> 2, lam = lane & 3;

    // K/V chunk prefetch registers (next chunk)
    uint4 pkh[4], pkl[4], pvh[4], pvl[4];

    auto prefetch = [&](int kc) {
#pragma unroll
        for (int t = 0; t < 4; t++) {
            const int i = tid + t * 256;
            pkh[t] = Kh[kc * 16 + i];
            pkl[t] = Kl[kc * 16 + i];
            const int vr = i >> 3;
            pvh[t] = *((const uint4*)(g_vth + ((size_t)bh * 128 + vr) * 2048 + kc) + (i & 7));
            pvl[t] = *((const uint4*)(g_vtl + ((size_t)bh * 128 + vr) * 2048 + kc) + (i & 7));
        }
    };
    auto commit = [&]() {
#pragma unroll
        for (int t = 0; t < 4; t++) {
            const int i = tid + t * 256;
            const uint32_t offK = (uint32_t)((i >> 4) * AT_ROW + (i & 15) * 16);
            *(uint4*)(sm + AT_SK_H + offK) = pkh[t];
            *(uint4*)(sm + AT_SK_L + offK) = pkl[t];
            const uint32_t offV = (uint32_t)((i >> 3) * AT_VROW + (i & 7) * 16);
            *(uint4*)(sm + AT_VT_H + offV) = pvh[t];
            *(uint4*)(sm + AT_VT_L + offV) = pvl[t];
        }
    };

    prefetch(0);

    for (int cidx = 0; cidx < 32; cidx++) {
        commit();
        __syncthreads();
        if (cidx + 1 < 32) prefetch((cidx + 1) * 64);

        // ---- S = Q @ K^T (3-term split) ----
        float S[8][4];
#pragma unroll
        for (int t = 0; t < 8; t++)
#pragma unroll
            for (int j = 0; j < 4; j++) S[t][j] = 0.0f;

#pragma unroll
        for (int kk = 0; kk < 8; kk++) {
            uint32_t ah[4], al[4];
            ldsm4(ah, sb + AT_SQ_H + aOff + kk * 32);
            ldsm4(al, sb + AT_SQ_L + aOff + kk * 32);
#pragma unroll
            for (int kg = 0; kg < 4; kg++) {
                uint32_t kbh[4], kbl[4];
                ldsm4(kbh, sb + AT_SK_H + bOff + kg * (16 * AT_ROW) + kk * 32);
                ldsm4(kbl, sb + AT_SK_L + bOff + kg * (16 * AT_ROW) + kk * 32);
                mma16816(S[2 * kg],     ah, kbh + 0);
                mma16816(S[2 * kg + 1], ah, kbh + 2);
                mma16816(S[2 * kg],     ah, kbl + 0);
                mma16816(S[2 * kg + 1], ah, kbl + 2);
                mma16816(S[2 * kg],     al, kbh + 0);
                mma16816(S[2 * kg + 1], al, kbh + 2);
            }
        }

        // ---- online softmax ----
        float mx0 = -30000.0f, mx1 = -30000.0f;
#pragma unroll
        for (int t = 0; t < 8; t++) {
            mx0 = fmaxf(mx0, fmaxf(S[t][0], S[t][1]));
            mx1 = fmaxf(mx1, fmaxf(S[t][2], S[t][3]));
        }
        mx0 = fmaxf(mx0, __shfl_xor_sync(0xffffffff, mx0, 1));
        mx0 = fmaxf(mx0, __shfl_xor_sync(0xffffffff, mx0, 2));
        mx1 = fmaxf(mx1, __shfl_xor_sync(0xffffffff, mx1, 1));
        mx1 = fmaxf(mx1, __shfl_xor_sync(0xffffffff, mx1, 2));

        const float nm0 = fmaxf(m0, mx0);
        const float nm1 = fmaxf(m1, mx1);
        const float al0 = __expf(fminf(m0 - nm0, 0.0f));
        const float al1 = __expf(fminf(m1 - nm1, 0.0f));
        m0 = nm0; m1 = nm1;

        float s0 = 0.0f, s1 = 0.0f;
#pragma unroll
        for (int t = 0; t < 8; t++) {
            S[t][0] = __expf(fminf(S[t][0] - m0, 0.0f));
            S[t][1] = __expf(fminf(S[t][1] - m0, 0.0f));
            S[t][2] = __expf(fminf(S[t][2] - m1, 0.0f));
            S[t][3] = __expf(fminf(S[t][3] - m1, 0.0f));
            s0 += S[t][0] + S[t][1];
            s1 += S[t][2] + S[t][3];
        }
        l0 = l0 * al0 + s0;
        l1 = l1 * al1 + s1;
#pragma unroll
        for (int nt = 0; nt < 16; nt++) {
            O[nt][0] *= al0; O[nt][1] *= al0;
            O[nt][2] *= al1; O[nt][3] *= al1;
        }

        // ---- P to warp-private smem (accumulator layout), bf16 hi/lo ----
#pragma unroll
        for (int t = 0; t < 8; t++) {
            const uint32_t cb = (uint32_t)(t * 16 + lam * 4);
            __nv_bfloat162 h0 = __floats2bfloat162_rn(S[t][0], S[t][1]);
            __nv_bfloat162 r0 = __floats2bfloat162_rn(S[t][0] - __bfloat162float(h0.x),
                                                      S[t][1] - __bfloat162float(h0.y));
            __nv_bfloat162 h1 = __floats2bfloat162_rn(S[t][2], S[t][3]);
            __nv_bfloat162 r1 = __floats2bfloat162_rn(S[t][2] - __bfloat162float(h1.x),
                                                      S[t][3] - __bfloat162float(h1.y));
            *(uint32_t*)(sm + (pwH - sb) + g * AT_VROW + cb)       = bf2_bits(h0);
            *(uint32_t*)(sm + (pwL - sb) + g * AT_VROW + cb)       = bf2_bits(r0);
            *(uint32_t*)(sm + (pwH - sb) + (g + 8) * AT_VROW + cb) = bf2_bits(h1);
            *(uint32_t*)(sm + (pwL - sb) + (g + 8) * AT_VROW + cb) = bf2_bits(r1);
        }
        __syncwarp();

        // ---- O += P @ V (3-term split) ----
#pragma unroll
        for (int kt = 0; kt < 4; kt++) {
            uint32_t ph[4], pl[4];
            ldsm4(ph, pwH + aP + kt * 32);
            ldsm4(pl, pwL + aP + kt * 32);
#pragma unroll
            for (int j = 0; j < 8; j++) {
                uint32_t vbh[4], vbl[4];
                ldsm4(vbh, sb + AT_VT_H + bV + j * (16 * AT_VROW) + kt * 32);
                ldsm4(vbl, sb + AT_VT_L + bV + j * (16 * AT_VROW) + kt * 32);
                mma16816(O[2 * j],     ph, vbh + 0);
                mma16816(O[2 * j + 1], ph, vbh + 2);
                mma16816(O[2 * j],     ph, vbl + 0);
                mma16816(O[2 * j + 1], ph, vbl + 2);
                mma16816(O[2 * j],     pl, vbh + 0);
                mma16816(O[2 * j + 1], pl, vbh + 2);
            }
        }
        __syncthreads();
    }

    // ---- epilogue ----
    l0 += __shfl_xor_sync(0xffffffff, l0, 1);
    l0 += __shfl_xor_sync(0xffffffff, l0, 2);
    l1 += __shfl_xor_sync(0xffffffff, l1, 1);
    l1 += __shfl_xor_sync(0xffffffff, l1, 2);
    const float inv0 = 1.0f / l0;
    const float inv1 = 1.0f / l1;

    const int bb = bh >> 4, hh2 = bh & 15;
    const int row0 = qb * 128 + w * 16 + g;
    const size_t base0 = (size_t)(bb * 2048 + row0) * 2048 + hh2 * 128 + lam * 2;
    const size_t base1 = base0 + (size_t)8 * 2048;

#pragma unroll
    for (int nt = 0; nt < 16; nt++) {
        float x0 = O[nt][0] * inv0, x1 = O[nt][1] * inv0;
        __nv_bfloat162 hx = __floats2bfloat162_rn(x0, x1);
        __nv_bfloat162 lx = __floats2bfloat162_rn(x0 - __bfloat162float(hx.x),
                                                  x1 - __bfloat162float(hx.y));
        *(uint32_t*)(g_att_hi + base0 + nt * 8) = bf2_bits(hx);
        *(uint32_t*)(g_att_lo + base0 + nt * 8) = bf2_bits(lx);

        float x2 = O[nt][2] * inv1, x3 = O[nt][3] * inv1;
        hx = __floats2bfloat162_rn(x2, x3);
        lx = __floats2bfloat162_rn(x2 - __bfloat162float(hx.x),
                                   x3 - __bfloat162float(hx.y));
        *(uint32_t*)(g_att_hi + base1 + nt * 8) = bf2_bits(hx);
        *(uint32_t*)(g_att_lo + base1 + nt * 8) = bf2_bits(lx);
    }
}

// ================= launch =================
extern "C" void kernel_launch(void* const* d_in, const int* in_sizes, int n_in,
                              void* d_out, int out_size)
{
    const float* x    = (const float*)d_in[0];
    const float* Wqkv = (const float*)d_in[1];
    const float* bqkv = (const float*)d_in[2];
    const float* Wo   = (const float*)d_in[3];
    const float* bo   = (const float*)d_in[4];
    float* out = (float*)d_out;

    __nv_bfloat16 *xh, *xl, *ah, *al, *wqh, *wql, *woh, *wol;
    cudaGetSymbolAddress((void**)&xh, g_x_hi);
    cudaGetSymbolAddress((void**)&xl, g_x_lo);
    cudaGetSymbolAddress((void**)&ah, g_att_hi);
    cudaGetSymbolAddress((void**)&al, g_att_lo);
    cudaGetSymbolAddress((void**)&wqh, g_WqkvT_hi);
    cudaGetSymbolAddress((void**)&wql, g_WqkvT_lo);
    cudaGetSymbolAddress((void**)&woh, g_WoT_hi);
    cudaGetSymbolAddress((void**)&wol, g_WoT_lo);

    cudaFuncSetAttribute(gemm_tc, cudaFuncAttributeMaxDynamicSharedMemorySize, G_SMEM);
    cudaFuncSetAttribute(gemm_qkv_rope, cudaFuncAttributeMaxDynamicSharedMemorySize, G_SMEM);
    cudaFuncSetAttribute(attn_tc, cudaFuncAttributeMaxDynamicSharedMemorySize, AT_SMEM);

    // prep
    split_convert<<<(4096 * 2048) / 256, 256>>>(x, xh, xl, 4096 * 2048);
    transpose_split<<<dim3(6144 / 32, 2048 / 32), dim3(32, 8)>>>(Wqkv, wqh, wql, 2048, 6144);
    transpose_split<<<dim3(2048 / 32, 2048 / 32), dim3(32, 8)>>>(Wo, woh, wol, 2048, 2048);

    // 1) QKV projection + fused RoPE/head-split/V-transpose
    gemm_qkv_rope<<<dim3(48, 32), 256, G_SMEM>>>(xh, xl, wqh, wql, bqkv);

    // 2) Tensor-core flash attention
    attn_tc<<<dim3(16, 32), 256, AT_SMEM>>>();

    // 3) Output projection
    gemm_tc<<<dim3(16, 32), 256, G_SMEM>>>(ah, al, woh, wol, bo, out, 2048, 2048);
}

// round 8
// speedup vs baseline: 5.4081x; 1.1266x over previous
#include <cuda_runtime.h>
#include <cuda_bf16.h>
#include <cstdint>
#include <math.h>

// ================= scratch =================
__device__ __nv_bfloat16 g_x_hi[4096 * 2048];
__device__ __nv_bfloat16 g_x_lo[4096 * 2048];
__device__ __nv_bfloat16 g_att_hi[4096 * 2048];
__device__ __nv_bfloat16 g_att_lo[4096 * 2048];
__device__ __nv_bfloat16 g_WqkvT_hi[6144 * 2048];
__device__ __nv_bfloat16 g_WqkvT_lo[6144 * 2048];
__device__ __nv_bfloat16 g_WoT_hi[2048 * 2048];
__device__ __nv_bfloat16 g_WoT_lo[2048 * 2048];
__device__ __nv_bfloat16 g_qh[4096 * 2048];
__device__ __nv_bfloat16 g_ql[4096 * 2048];
__device__ __nv_bfloat16 g_kh[4096 * 2048];
__device__ __nv_bfloat16 g_kl[4096 * 2048];
// V transposed per head: [b*h, dim=128, s=2048]
__device__ __nv_bfloat16 g_vth[4096 * 2048];
__device__ __nv_bfloat16 g_vtl[4096 * 2048];

// ================= helpers =================
__device__ __forceinline__ uint32_t smem_u32(const void* p) {
    uint32_t a;
    asm("{ .reg .u64 t; cvta.to.shared.u64 t, %1; cvt.u32.u64 %0, t; }" : "=r"(a) : "l"(p));
    return a;
}
__device__ __forceinline__ void ldsm4(uint32_t (&r)[4], uint32_t addr) {
    asm volatile("ldmatrix.sync.aligned.m8n8.x4.shared.b16 {%0,%1,%2,%3}, [%4];"
        : "=r"(r[0]), "=r"(r[1]), "=r"(r[2]), "=r"(r[3]) : "r"(addr));
}
__device__ __forceinline__ void mma16816(float* c, const uint32_t* a, const uint32_t* b) {
    asm volatile("mma.sync.aligned.m16n8k16.row.col.f32.bf16.bf16.f32 "
        "{%0,%1,%2,%3}, {%4,%5,%6,%7}, {%8,%9}, {%0,%1,%2,%3};"
        : "+f"(c[0]), "+f"(c[1]), "+f"(c[2]), "+f"(c[3])
        : "r"(a[0]), "r"(a[1]), "r"(a[2]), "r"(a[3]), "r"(b[0]), "r"(b[1]));
}
__device__ __forceinline__ void cp16(uint32_t sa, const void* g) {
    asm volatile("cp.async.cg.shared.global [%0], [%1], 16;" :: "r"(sa), "l"(g));
}
#define CP_COMMIT() asm volatile("cp.async.commit_group;" ::: "memory")
#define CP_WAIT0()  asm volatile("cp.async.wait_group 0;" ::: "memory")
__device__ __forceinline__ uint32_t bf2_bits(__nv_bfloat162 v) {
    return *reinterpret_cast<uint32_t*>(&v);
}
__device__ __forceinline__ void stage_split(__nv_bfloat16* hi, __nv_bfloat16* lo,
                                            int off, float v) {
    __nv_bfloat16 h = __float2bfloat16(v);
    hi[off] = h;
    lo[off] = __float2bfloat16(v - __bfloat162float(h));
}

// ================= prep kernels =================
__global__ void split_convert(const float* __restrict__ in,
                              __nv_bfloat16* __restrict__ hi, __nv_bfloat16* __restrict__ lo, int n) {
    int i = blockIdx.x * blockDim.x + threadIdx.x;
    if (i >= n) return;
    float v = in[i];
    __nv_bfloat16 h = __float2bfloat16(v);
    hi[i] = h;
    lo[i] = __float2bfloat16(v - __bfloat162float(h));
}

__global__ void transpose_split(const float* __restrict__ W,
                                __nv_bfloat16* __restrict__ Thi, __nv_bfloat16* __restrict__ Tlo,
                                int K, int N) {
    __shared__ float s[32][33];
    int n0 = blockIdx.x * 32, k0 = blockIdx.y * 32;
    int tx = threadIdx.x, ty = threadIdx.y;
#pragma unroll
    for (int j = 0; j < 32; j += 8)
        s[ty + j][tx] = W[(size_t)(k0 + ty + j) * N + n0 + tx];
    __syncthreads();
#pragma unroll
    for (int j = 0; j < 32; j += 8) {
        float v = s[tx][ty + j];
        __nv_bfloat16 h = __float2bfloat16(v);
        size_t o = (size_t)(n0 + ty + j) * K + k0 + tx;
        Thi[o] = h;
        Tlo[o] = __float2bfloat16(v - __bfloat162float(h));
    }
}

// ================= GEMM mainloop (cp.async double-buffered) =================
#define STG_A   0
#define STG_AL  10240
#define STG_B   20480
#define STG_BL  30720
#define STG_BYTES 40960
#define G_SMEM (2 * STG_BYTES)

__device__ __forceinline__ void gemm_cp_chunk(
    uint32_t st,
    const __nv_bfloat16* __restrict__ Ah, const __nv_bfloat16* __restrict__ Al,
    const __nv_bfloat16* __restrict__ Bh, const __nv_bfloat16* __restrict__ Bl,
    int bm, int bn, int K, int kc, int tid)
{
#pragma unroll
    for (int t = 0; t < 2; t++) {
        const int i = tid + t * 256;
        const int r = i >> 2, c = (i & 3) * 8;
        const uint32_t o = (uint32_t)(r * 80 + (i & 3) * 16);
        cp16(st + STG_A  + o, Ah + (size_t)(bm + r) * K + kc + c);
        cp16(st + STG_AL + o, Al + (size_t)(bm + r) * K + kc + c);
        cp16(st + STG_B  + o, Bh + (size_t)(bn + r) * K + kc + c);
        cp16(st + STG_BL + o, Bl + (size_t)(bn + r) * K + kc + c);
    }
}

#define GEMM_MAINLOOP(Ah, Al, Bh, Bl, K)                                            \
    float acc[4][4][4];                                                             \
    _Pragma("unroll") for (int i = 0; i < 4; i++)                                   \
    _Pragma("unroll") for (int j = 0; j < 4; j++)                                   \
    _Pragma("unroll") for (int k = 0; k < 4; k++) acc[i][j][k] = 0.0f;              \
    const uint32_t sb0 = smem_u32(smem);                                            \
    const uint32_t aOff = (uint32_t)((wm * 64 + (lane & 15)) * 80 + ((lane >> 4) << 4)); \
    const uint32_t bOff = (uint32_t)((wn * 32 + (lane & 7) + ((lane >> 4) << 3)) * 80    \
                                     + (((lane >> 3) & 1) << 4));                   \
    const int nch = (K) / 32;                                                       \
    gemm_cp_chunk(sb0, Ah, Al, Bh, Bl, bm, bn, K, 0, tid);                          \
    CP_COMMIT();                                                                    \
    for (int c = 0; c < nch; c++) {                                                 \
        CP_WAIT0();                                                                 \
        __syncthreads();                                                            \
        if (c + 1 < nch) {                                                          \
            gemm_cp_chunk(sb0 + (uint32_t)(((c + 1) & 1) * STG_BYTES),              \
                          Ah, Al, Bh, Bl, bm, bn, K, (c + 1) * 32, tid);            \
            CP_COMMIT();                                                            \
        }                                                                           \
        const uint32_t sb = sb0 + (uint32_t)((c & 1) * STG_BYTES);                  \
        _Pragma("unroll")                                                           \
        for (int ks = 0; ks < 2; ks++) {                                            \
            const uint32_t ko = (uint32_t)(ks * 32);                                \
            uint32_t a0[4][4], b0[2][4];                                            \
            _Pragma("unroll") for (int mi = 0; mi < 4; mi++)                        \
                ldsm4(a0[mi], sb + STG_A + aOff + mi * 1280 + ko);                  \
            _Pragma("unroll") for (int nj = 0; nj < 2; nj++)                        \
                ldsm4(b0[nj], sb + STG_B + bOff + nj * 1280 + ko);                  \
            _Pragma("unroll") for (int mi = 0; mi < 4; mi++)                        \
            _Pragma("unroll") for (int ni = 0; ni < 4; ni++)                        \
                mma16816(acc[mi][ni], a0[mi], &b0[ni >> 1][(ni & 1) * 2]);          \
            uint32_t b1[2][4];                                                      \
            _Pragma("unroll") for (int nj = 0; nj < 2; nj++)                        \
                ldsm4(b1[nj], sb + STG_BL + bOff + nj * 1280 + ko);                 \
            _Pragma("unroll") for (int mi = 0; mi < 4; mi++)                        \
            _Pragma("unroll") for (int ni = 0; ni < 4; ni++)                        \
                mma16816(acc[mi][ni], a0[mi], &b1[ni >> 1][(ni & 1) * 2]);          \
            uint32_t a1[4][4];                                                      \
            _Pragma("unroll") for (int mi = 0; mi < 4; mi++)                        \
                ldsm4(a1[mi], sb + STG_AL + aOff + mi * 1280 + ko);                 \
            _Pragma("unroll") for (int mi = 0; mi < 4; mi++)                        \
            _Pragma("unroll") for (int ni = 0; ni < 4; ni++)                        \
                mma16816(acc[mi][ni], a1[mi], &b0[ni >> 1][(ni & 1) * 2]);          \
        }                                                                           \
    }

// ================= GEMM #2: out-proj (float out + bias) =================
__global__ __launch_bounds__(256, 2) void gemm_tc(
    const __nv_bfloat16* __restrict__ Ah, const __nv_bfloat16* __restrict__ Al,
    const __nv_bfloat16* __restrict__ Bh, const __nv_bfloat16* __restrict__ Bl,
    const float* __restrict__ bias, float* __restrict__ C, int N, int K)
{
    extern __shared__ char smem[];
    const int tid = threadIdx.x;
    const int lane = tid & 31;
    const int wid = tid >> 5;
    const int wm = wid & 1;
    const int wn = wid >> 1;
    const int bm = blockIdx.y * 128;
    const int bn = blockIdx.x * 128;

    GEMM_MAINLOOP(Ah, Al, Bh, Bl, K)

    const int rbase = bm + wm * 64 + (lane >> 2);
    const int cbase = bn + wn * 32 + (lane & 3) * 2;
#pragma unroll
    for (int mi = 0; mi < 4; mi++) {
#pragma unroll
        for (int ni = 0; ni < 4; ni++) {
            const int col = cbase + ni * 8;
            const float2 bv = *(const float2*)(bias + col);
            const int r0 = rbase + mi * 16;
            float2 o0, o1;
            o0.x = acc[mi][ni][0] + bv.x; o0.y = acc[mi][ni][1] + bv.y;
            o1.x = acc[mi][ni][2] + bv.x; o1.y = acc[mi][ni][3] + bv.y;
            *(float2*)(C + (size_t)r0 * N + col) = o0;
            *(float2*)(C + (size_t)(r0 + 8) * N + col) = o1;
        }
    }
}

// ================= GEMM #1: QKV projection + fused RoPE/split/V-transpose =================
__global__ __launch_bounds__(256, 2) void gemm_qkv_rope(
    const __nv_bfloat16* __restrict__ Ah, const __nv_bfloat16* __restrict__ Al,
    const __nv_bfloat16* __restrict__ Bh, const __nv_bfloat16* __restrict__ Bl,
    const float* __restrict__ bias)
{
    extern __shared__ char smem[];
    const int tid = threadIdx.x;
    const int lane = tid & 31;
    const int wid = tid >> 5;
    const int wm = wid & 1;
    const int wn = wid >> 1;
    const int bm = blockIdx.y * 128;
    const int bn = blockIdx.x * 128;
    const int K = 2048;

    GEMM_MAINLOOP(Ah, Al, Bh, Bl, K)

    __syncthreads();  // mainloop smem reads done before staging overwrites

    const int seg   = bn >> 11;          // 0=Q 1=K 2=V
    const int head  = (bn & 2047) >> 7;
    const int bidx  = bm >> 11;
    const int s_base = bm & 2047;
    const int bhh   = bidx * 16 + head;

    __nv_bfloat16* sh_hi = (__nv_bfloat16*)smem;            // 128x128 bf16
    __nv_bfloat16* sh_lo = (__nv_bfloat16*)(smem + 32768);

    const int rl = wm * 64 + (lane >> 2);
    const int cb = wn * 32 + (lane & 3) * 2;
    const float qscale = 0.08838834764831845f;

    // hoist theta per ni (4 distinct j values per thread)
    float thetas[4];
    if (seg < 2) {
#pragma unroll
        for (int ni = 0; ni < 4; ni++) {
            const int j = (cb + ni * 8) >> 1;
            thetas[ni] = 1.0f / powf(10000.0f, (float)(2 * j) / 128.0f);
        }
    }

#pragma unroll
    for (int mi = 0; mi < 4; mi++) {
#pragma unroll
        for (int ni = 0; ni < 4; ni++) {
            const int c = cb + ni * 8;
            const float b0 = bias[bn + c], b1 = bias[bn + c + 1];
            float v0 = acc[mi][ni][0] + b0, v1 = acc[mi][ni][1] + b1;
            float w0 = acc[mi][ni][2] + b0, w1 = acc[mi][ni][3] + b1;
            const int r0 = rl + mi * 16, r1 = r0 + 8;
            if (seg < 2) {
                const int j = c >> 1;
                const float theta = thetas[ni];
                float sn0, cs0, sn1, cs1;
                sincosf((float)(s_base + r0) * theta, &sn0, &cs0);
                sincosf((float)(s_base + r1) * theta, &sn1, &cs1);
                float a0 = v0 * cs0 - v1 * sn0, o0 = v0 * sn0 + v1 * cs0;
                float a1 = w0 * cs1 - w1 * sn1, o1 = w0 * sn1 + w1 * cs1;
                if (seg == 0) { a0 *= qscale; o0 *= qscale; a1 *= qscale; o1 *= qscale; }
                stage_split(sh_hi, sh_lo, r0 * 128 + j,      a0);
                stage_split(sh_hi, sh_lo, r0 * 128 + j + 64, o0);
                stage_split(sh_hi, sh_lo, r1 * 128 + j,      a1);
                stage_split(sh_hi, sh_lo, r1 * 128 + j + 64, o1);
            } else {
                stage_split(sh_hi, sh_lo, c * 128 + r0,       v0);
                stage_split(sh_hi, sh_lo, (c + 1) * 128 + r0, v1);
                stage_split(sh_hi, sh_lo, c * 128 + r1,       w0);
                stage_split(sh_hi, sh_lo, (c + 1) * 128 + r1, w1);
            }
        }
    }
    __syncthreads();

    if (seg < 2) {
        __nv_bfloat16* Hd = (seg == 0) ? g_qh : g_kh;
        __nv_bfloat16* Ld = (seg == 0) ? g_ql : g_kl;
        for (int i = tid; i < 2048; i += 256) {
            const int row = i >> 4, q = i & 15;
            const size_t eo = ((size_t)bhh * 2048 + s_base + row) * 128 + q * 8;
            *(uint4*)(Hd + eo) = *(const uint4*)(sh_hi + row * 128 + q * 8);
            *(uint4*)(Ld + eo) = *(const uint4*)(sh_lo + row * 128 + q * 8);
        }
    } else {
        for (int i = tid; i < 2048; i += 256) {
            const int d = i >> 4, q = i & 15;
            const size_t eo = ((size_t)(bhh * 128 + d)) * 2048 + s_base + q * 8;
            *(uint4*)(g_vth + eo) = *(const uint4*)(sh_hi + d * 128 + q * 8);
            *(uint4*)(g_vtl + eo) = *(const uint4*)(sh_lo + d * 128 + q * 8);
        }
    }
}

// ================= flash attention: Q in regs, cp.async double-buffered K/V =================
#define AT_ROW   272
#define AT_VROW  144
// K stage s: base s*34816 (hi), +17408 (lo).  V stage s: 69632 + s*36864 (hi), +18432 (lo)
#define AT_P_H   143360
#define AT_P_L   161792
#define AT_SMEM  180224

__global__ __launch_bounds__(256) void attn_tc()
{
    extern __shared__ char sm[];
    const uint32_t sb = smem_u32(sm);
    const int tid = threadIdx.x;
    const int lane = tid & 31;
    const int w = tid >> 5;
    const int qb = blockIdx.x;
    const int bh = blockIdx.y;

    const size_t hbase = (size_t)bh * 2048 * 128;
    const uint4* Qh = (const uint4*)(g_qh + hbase + (size_t)qb * 128 * 128);
    const uint4* Ql = (const uint4*)(g_ql + hbase + (size_t)qb * 128 * 128);
    const __nv_bfloat16* Khp = g_kh + hbase;
    const __nv_bfloat16* Klp = g_kl + hbase;
    const __nv_bfloat16* Vth = g_vth + (size_t)bh * 128 * 2048;
    const __nv_bfloat16* Vtl = g_vtl + (size_t)bh * 128 * 2048;

    // stage Q (hi at 0, lo at 34816; reused as K buffers afterwards)
    for (int i = tid; i < 2048; i += 256) {
        const uint32_t off = (uint32_t)((i >> 4) * AT_ROW + (i & 15) * 16);
        *(uint4*)(sm + off) = Qh[i];
        *(uint4*)(sm + 34816 + off) = Ql[i];
    }
    __syncthreads();

    // Q fragments -> registers (persist whole kernel)
    const uint32_t aOff = (uint32_t)((w * 16 + (lane & 15)) * AT_ROW + ((lane >> 4) << 4));
    uint32_t qfh[8][4], qfl[8][4];
#pragma unroll
    for (int kk = 0; kk < 8; kk++) {
        ldsm4(qfh[kk], sb + aOff + kk * 32);
        ldsm4(qfl[kk], sb + 34816 + aOff + kk * 32);
    }
    __syncthreads();

    const uint32_t bOff = (uint32_t)(((lane & 7) + ((lane >> 4) << 3)) * AT_ROW
                                     + (((lane >> 3) & 1) << 4));
    const uint32_t bV   = (uint32_t)(((lane & 7) + ((lane >> 4) << 3)) * AT_VROW
                                     + (((lane >> 3) & 1) << 4));
    const uint32_t aP   = (uint32_t)((lane & 15) * AT_VROW + ((lane >> 4) << 4));
    const uint32_t pwH  = sb + AT_P_H + (uint32_t)(w * 16 * AT_VROW);
    const uint32_t pwL  = sb + AT_P_L + (uint32_t)(w * 16 * AT_VROW);

    float O[16][4];
#pragma unroll
    for (int i = 0; i < 16; i++)
#pragma unroll
        for (int j = 0; j < 4; j++) O[i][j] = 0.0f;
    float m0 = -30000.0f, m1 = -30000.0f, l0 = 0.0f, l1 = 0.0f;
    const int g = lane >> 2, lam = lane & 3;

    auto load_chunk = [&](int kc, int st) {
        const uint32_t kbase = sb + (uint32_t)(st * 34816);
        const uint32_t vbase = sb + 69632u + (uint32_t)(st * 36864);
#pragma unroll
        for (int t = 0; t < 4; t++) {
            const int i = tid + t * 256;
            const int kr = i >> 4, kq = i & 15;
            cp16(kbase + kr * AT_ROW + kq * 16,         Khp + (size_t)(kc + kr) * 128 + kq * 8);
            cp16(kbase + 17408 + kr * AT_ROW + kq * 16, Klp + (size_t)(kc + kr) * 128 + kq * 8);
            const int vr = i >> 3, vq = i & 7;
            cp16(vbase + vr * AT_VROW + vq * 16,         Vth + (size_t)vr * 2048 + kc + vq * 8);
            cp16(vbase + 18432 + vr * AT_VROW + vq * 16, Vtl + (size_t)vr * 2048 + kc + vq * 8);
        }
    };

    load_chunk(0, 0);
    CP_COMMIT();

    for (int cidx = 0; cidx < 32; cidx++) {
        CP_WAIT0();
        __syncthreads();
        if (cidx + 1 < 32) {
            load_chunk((cidx + 1) * 64, (cidx + 1) & 1);
            CP_COMMIT();
        }
        const uint32_t kst = sb + (uint32_t)((cidx & 1) * 34816);
        const uint32_t vst = sb + 69632u + (uint32_t)((cidx & 1) * 36864);

        // ---- S = Q @ K^T (3-term split), Q from registers ----
        float S[8][4];
#pragma unroll
        for (int t = 0; t < 8; t++)
#pragma unroll
            for (int j = 0; j < 4; j++) S[t][j] = 0.0f;

#pragma unroll
        for (int kk = 0; kk < 8; kk++) {
#pragma unroll
            for (int kg = 0; kg < 4; kg++) {
                uint32_t kbh[4], kbl[4];
                ldsm4(kbh, kst + bOff + kg * (16 * AT_ROW) + kk * 32);
                ldsm4(kbl, kst + 17408 + bOff + kg * (16 * AT_ROW) + kk * 32);
                mma16816(S[2 * kg],     qfh[kk], kbh + 0);
                mma16816(S[2 * kg + 1], qfh[kk], kbh + 2);
                mma16816(S[2 * kg],     qfh[kk], kbl + 0);
                mma16816(S[2 * kg + 1], qfh[kk], kbl + 2);
                mma16816(S[2 * kg],     qfl[kk], kbh + 0);
                mma16816(S[2 * kg + 1], qfl[kk], kbh + 2);
            }
        }

        // ---- online softmax ----
        float mx0 = -30000.0f, mx1 = -30000.0f;
#pragma unroll
        for (int t = 0; t < 8; t++) {
            mx0 = fmaxf(mx0, fmaxf(S[t][0], S[t][1]));
            mx1 = fmaxf(mx1, fmaxf(S[t][2], S[t][3]));
        }
        mx0 = fmaxf(mx0, __shfl_xor_sync(0xffffffff, mx0, 1));
        mx0 = fmaxf(mx0, __shfl_xor_sync(0xffffffff, mx0, 2));
        mx1 = fmaxf(mx1, __shfl_xor_sync(0xffffffff, mx1, 1));
        mx1 = fmaxf(mx1, __shfl_xor_sync(0xffffffff, mx1, 2));

        const float nm0 = fmaxf(m0, mx0);
        const float nm1 = fmaxf(m1, mx1);
        const float al0 = __expf(fminf(m0 - nm0, 0.0f));
        const float al1 = __expf(fminf(m1 - nm1, 0.0f));
        m0 = nm0; m1 = nm1;

        float s0 = 0.0f, s1 = 0.0f;
#pragma unroll
        for (int t = 0; t < 8; t++) {
            S[t][0] = __expf(fminf(S[t][0] - m0, 0.0f));
            S[t][1] = __expf(fminf(S[t][1] - m0, 0.0f));
            S[t][2] = __expf(fminf(S[t][2] - m1, 0.0f));
            S[t][3] = __expf(fminf(S[t][3] - m1, 0.0f));
            s0 += S[t][0] + S[t][1];
            s1 += S[t][2] + S[t][3];
        }
        l0 = l0 * al0 + s0;
        l1 = l1 * al1 + s1;
#pragma unroll
        for (int nt = 0; nt < 16; nt++) {
            O[nt][0] *= al0; O[nt][1] *= al0;
            O[nt][2] *= al1; O[nt][3] *= al1;
        }

        // ---- P -> warp-private smem (accumulator layout) ----
#pragma unroll
        for (int t = 0; t < 8; t++) {
            const uint32_t cb = (uint32_t)(t * 16 + lam * 4);
            __nv_bfloat162 h0 = __floats2bfloat162_rn(S[t][0], S[t][1]);
            __nv_bfloat162 r0 = __floats2bfloat162_rn(S[t][0] - __bfloat162float(h0.x),
                                                      S[t][1] - __bfloat162float(h0.y));
            __nv_bfloat162 h1 = __floats2bfloat162_rn(S[t][2], S[t][3]);
            __nv_bfloat162 r1 = __floats2bfloat162_rn(S[t][2] - __bfloat162float(h1.x),
                                                      S[t][3] - __bfloat162float(h1.y));
            *(uint32_t*)(sm + (pwH - sb) + g * AT_VROW + cb)       = bf2_bits(h0);
            *(uint32_t*)(sm + (pwL - sb) + g * AT_VROW + cb)       = bf2_bits(r0);
            *(uint32_t*)(sm + (pwH - sb) + (g + 8) * AT_VROW + cb) = bf2_bits(h1);
            *(uint32_t*)(sm + (pwL - sb) + (g + 8) * AT_VROW + cb) = bf2_bits(r1);
        }
        __syncwarp();

        // ---- O += P @ V (3-term split) ----
#pragma unroll
        for (int kt = 0; kt < 4; kt++) {
            uint32_t ph[4], pl[4];
            ldsm4(ph, pwH + aP + kt * 32);
            ldsm4(pl, pwL + aP + kt * 32);
#pragma unroll
            for (int j = 0; j < 8; j++) {
                uint32_t vbh[4], vbl[4];
                ldsm4(vbh, vst + bV + j * (16 * AT_VROW) + kt * 32);
                ldsm4(vbl, vst + 18432 + bV + j * (16 * AT_VROW) + kt * 32);
                mma16816(O[2 * j],     ph, vbh + 0);
                mma16816(O[2 * j + 1], ph, vbh + 2);
                mma16816(O[2 * j],     ph, vbl + 0);
                mma16816(O[2 * j + 1], ph, vbl + 2);
                mma16816(O[2 * j],     pl, vbh + 0);
                mma16816(O[2 * j + 1], pl, vbh + 2);
            }
        }
        __syncwarp();
    }

    // ---- epilogue ----
    l0 += __shfl_xor_sync(0xffffffff, l0, 1);
    l0 += __shfl_xor_sync(0xffffffff, l0, 2);
    l1 += __shfl_xor_sync(0xffffffff, l1, 1);
    l1 += __shfl_xor_sync(0xffffffff, l1, 2);
    const float inv0 = 1.0f / l0;
    const float inv1 = 1.0f / l1;

    const int bb = bh >> 4, hh2 = bh & 15;
    const int row0 = qb * 128 + w * 16 + g;
    const size_t base0 = (size_t)(bb * 2048 + row0) * 2048 + hh2 * 128 + lam * 2;
    const size_t base1 = base0 + (size_t)8 * 2048;

#pragma unroll
    for (int nt = 0; nt < 16; nt++) {
        float x0 = O[nt][0] * inv0, x1 = O[nt][1] * inv0;
        __nv_bfloat162 hx = __floats2bfloat162_rn(x0, x1);
        __nv_bfloat162 lx = __floats2bfloat162_rn(x0 - __bfloat162float(hx.x),
                                                  x1 - __bfloat162float(hx.y));
        *(uint32_t*)(g_att_hi + base0 + nt * 8) = bf2_bits(hx);
        *(uint32_t*)(g_att_lo + base0 + nt * 8) = bf2_bits(lx);

        float x2 = O[nt][2] * inv1, x3 = O[nt][3] * inv1;
        hx = __floats2bfloat162_rn(x2, x3);
        lx = __floats2bfloat162_rn(x2 - __bfloat162float(hx.x),
                                   x3 - __bfloat162float(hx.y));
        *(uint32_t*)(g_att_hi + base1 + nt * 8) = bf2_bits(hx);
        *(uint32_t*)(g_att_lo + base1 + nt * 8) = bf2_bits(lx);
    }
}

// ================= launch =================
extern "C" void kernel_launch(void* const* d_in, const int* in_sizes, int n_in,
                              void* d_out, int out_size)
{
    const float* x    = (const float*)d_in[0];
    const float* Wqkv = (const float*)d_in[1];
    const float* bqkv = (const float*)d_in[2];
    const float* Wo   = (const float*)d_in[3];
    const float* bo   = (const float*)d_in[4];
    float* out = (float*)d_out;

    __nv_bfloat16 *xh, *xl, *ah, *al, *wqh, *wql, *woh, *wol;
    cudaGetSymbolAddress((void**)&xh, g_x_hi);
    cudaGetSymbolAddress((void**)&xl, g_x_lo);
    cudaGetSymbolAddress((void**)&ah, g_att_hi);
    cudaGetSymbolAddress((void**)&al, g_att_lo);
    cudaGetSymbolAddress((void**)&wqh, g_WqkvT_hi);
    cudaGetSymbolAddress((void**)&wql, g_WqkvT_lo);
    cudaGetSymbolAddress((void**)&woh, g_WoT_hi);
    cudaGetSymbolAddress((void**)&wol, g_WoT_lo);

    cudaFuncSetAttribute(gemm_tc, cudaFuncAttributeMaxDynamicSharedMemorySize, G_SMEM);
    cudaFuncSetAttribute(gemm_qkv_rope, cudaFuncAttributeMaxDynamicSharedMemorySize, G_SMEM);
    cudaFuncSetAttribute(attn_tc, cudaFuncAttributeMaxDynamicSharedMemorySize, AT_SMEM);

    // prep
    split_convert<<<(4096 * 2048) / 256, 256>>>(x, xh, xl, 4096 * 2048);
    transpose_split<<<dim3(6144 / 32, 2048 / 32), dim3(32, 8)>>>(Wqkv, wqh, wql, 2048, 6144);
    transpose_split<<<dim3(2048 / 32, 2048 / 32), dim3(32, 8)>>>(Wo, woh, wol, 2048, 2048);

    // 1) QKV projection + fused RoPE/head-split/V-transpose
    gemm_qkv_rope<<<dim3(48, 32), 256, G_SMEM>>>(xh, xl, wqh, wql, bqkv);

    // 2) Tensor-core flash attention
    attn_tc<<<dim3(16, 32), 256, AT_SMEM>>>();

    // 3) Output projection
    gemm_tc<<<dim3(16, 32), 256, G_SMEM>>>(ah, al, woh, wol, bo, out, 2048, 2048);
}

// round 9
// speedup vs baseline: 5.4720x; 1.0118x over previous
#include <cuda_runtime.h>
#include <cuda_bf16.h>
#include <cstdint>
#include <math.h>

// ================= scratch =================
__device__ __nv_bfloat16 g_x_hi[4096 * 2048];
__device__ __nv_bfloat16 g_x_lo[4096 * 2048];
__device__ __nv_bfloat16 g_att_hi[4096 * 2048];
__device__ __nv_bfloat16 g_att_lo[4096 * 2048];
__device__ __nv_bfloat16 g_WqkvT_hi[6144 * 2048];
__device__ __nv_bfloat16 g_WqkvT_lo[6144 * 2048];
__device__ __nv_bfloat16 g_WoT_hi[2048 * 2048];
__device__ __nv_bfloat16 g_WoT_lo[2048 * 2048];
__device__ __nv_bfloat16 g_qh[4096 * 2048];
__device__ __nv_bfloat16 g_ql[4096 * 2048];
__device__ __nv_bfloat16 g_kh[4096 * 2048];
__device__ __nv_bfloat16 g_kl[4096 * 2048];
__device__ __nv_bfloat16 g_vth[4096 * 2048];
__device__ __nv_bfloat16 g_vtl[4096 * 2048];
__device__ float2 g_rope[2048 * 64];   // (cos, sin) per (s, j)

// ================= helpers =================
__device__ __forceinline__ uint32_t smem_u32(const void* p) {
    uint32_t a;
    asm("{ .reg .u64 t; cvta.to.shared.u64 t, %1; cvt.u32.u64 %0, t; }" : "=r"(a) : "l"(p));
    return a;
}
__device__ __forceinline__ void ldsm4(uint32_t (&r)[4], uint32_t addr) {
    asm volatile("ldmatrix.sync.aligned.m8n8.x4.shared.b16 {%0,%1,%2,%3}, [%4];"
        : "=r"(r[0]), "=r"(r[1]), "=r"(r[2]), "=r"(r[3]) : "r"(addr));
}
__device__ __forceinline__ void mma16816(float* c, const uint32_t* a, const uint32_t* b) {
    asm volatile("mma.sync.aligned.m16n8k16.row.col.f32.bf16.bf16.f32 "
        "{%0,%1,%2,%3}, {%4,%5,%6,%7}, {%8,%9}, {%0,%1,%2,%3};"
        : "+f"(c[0]), "+f"(c[1]), "+f"(c[2]), "+f"(c[3])
        : "r"(a[0]), "r"(a[1]), "r"(a[2]), "r"(a[3]), "r"(b[0]), "r"(b[1]));
}
__device__ __forceinline__ void cp16(uint32_t sa, const void* g) {
    asm volatile("cp.async.cg.shared.global [%0], [%1], 16;" :: "r"(sa), "l"(g));
}
#define CP_COMMIT() asm volatile("cp.async.commit_group;" ::: "memory")
#define CP_WAIT0()  asm volatile("cp.async.wait_group 0;" ::: "memory")
__device__ __forceinline__ uint32_t bf2_bits(__nv_bfloat162 v) {
    return *reinterpret_cast<uint32_t*>(&v);
}
__device__ __forceinline__ void stage_split(__nv_bfloat16* hi, __nv_bfloat16* lo,
                                            int off, float v) {
    __nv_bfloat16 h = __float2bfloat16(v);
    hi[off] = h;
    lo[off] = __float2bfloat16(v - __bfloat162float(h));
}

// ================= prep kernels =================
__global__ void split_convert(const float* __restrict__ in,
                              __nv_bfloat16* __restrict__ hi, __nv_bfloat16* __restrict__ lo, int n) {
    int i = blockIdx.x * blockDim.x + threadIdx.x;
    if (i >= n) return;
    float v = in[i];
    __nv_bfloat16 h = __float2bfloat16(v);
    hi[i] = h;
    lo[i] = __float2bfloat16(v - __bfloat162float(h));
}

__global__ void rope_table_kernel()
{
    const int idx = blockIdx.x * blockDim.x + threadIdx.x;  // < 2048*64
    const int j = idx & 63;
    const int s = idx >> 6;
    const float theta = 1.0f / powf(10000.0f, (float)(2 * j) / 128.0f);
    float sn, cs;
    sincosf((float)s * theta, &sn, &cs);
    g_rope[idx] = make_float2(cs, sn);
}

__global__ void transpose_split(const float* __restrict__ W,
                                __nv_bfloat16* __restrict__ Thi, __nv_bfloat16* __restrict__ Tlo,
                                int K, int N) {
    __shared__ float s[32][33];
    int n0 = blockIdx.x * 32, k0 = blockIdx.y * 32;
    int tx = threadIdx.x, ty = threadIdx.y;
#pragma unroll
    for (int j = 0; j < 32; j += 8)
        s[ty + j][tx] = W[(size_t)(k0 + ty + j) * N + n0 + tx];
    __syncthreads();
#pragma unroll
    for (int j = 0; j < 32; j += 8) {
        float v = s[tx][ty + j];
        __nv_bfloat16 h = __float2bfloat16(v);
        size_t o = (size_t)(n0 + ty + j) * K + k0 + tx;
        Thi[o] = h;
        Tlo[o] = __float2bfloat16(v - __bfloat162float(h));
    }
}

// ================= GEMM mainloop (cp.async double-buffered) =================
#define STG_A   0
#define STG_AL  10240
#define STG_B   20480
#define STG_BL  30720
#define STG_BYTES 40960
#define G_SMEM (2 * STG_BYTES)

__device__ __forceinline__ void gemm_cp_chunk(
    uint32_t st,
    const __nv_bfloat16* __restrict__ Ah, const __nv_bfloat16* __restrict__ Al,
    const __nv_bfloat16* __restrict__ Bh, const __nv_bfloat16* __restrict__ Bl,
    int bm, int bn, int K, int kc, int tid)
{
#pragma unroll
    for (int t = 0; t < 2; t++) {
        const int i = tid + t * 256;
        const int r = i >> 2, c = (i & 3) * 8;
        const uint32_t o = (uint32_t)(r * 80 + (i & 3) * 16);
        cp16(st + STG_A  + o, Ah + (size_t)(bm + r) * K + kc + c);
        cp16(st + STG_AL + o, Al + (size_t)(bm + r) * K + kc + c);
        cp16(st + STG_B  + o, Bh + (size_t)(bn + r) * K + kc + c);
        cp16(st + STG_BL + o, Bl + (size_t)(bn + r) * K + kc + c);
    }
}

#define GEMM_MAINLOOP(Ah, Al, Bh, Bl, K)                                            \
    float acc[4][4][4];                                                             \
    _Pragma("unroll") for (int i = 0; i < 4; i++)                                   \
    _Pragma("unroll") for (int j = 0; j < 4; j++)                                   \
    _Pragma("unroll") for (int k = 0; k < 4; k++) acc[i][j][k] = 0.0f;              \
    const uint32_t sb0 = smem_u32(smem);                                            \
    const uint32_t aOff = (uint32_t)((wm * 64 + (lane & 15)) * 80 + ((lane >> 4) << 4)); \
    const uint32_t bOff = (uint32_t)((wn * 32 + (lane & 7) + ((lane >> 4) << 3)) * 80    \
                                     + (((lane >> 3) & 1) << 4));                   \
    const int nch = (K) / 32;                                                       \
    gemm_cp_chunk(sb0, Ah, Al, Bh, Bl, bm, bn, K, 0, tid);                          \
    CP_COMMIT();                                                                    \
    for (int c = 0; c < nch; c++) {                                                 \
        CP_WAIT0();                                                                 \
        __syncthreads();                                                            \
        if (c + 1 < nch) {                                                          \
            gemm_cp_chunk(sb0 + (uint32_t)(((c + 1) & 1) * STG_BYTES),              \
                          Ah, Al, Bh, Bl, bm, bn, K, (c + 1) * 32, tid);            \
            CP_COMMIT();                                                            \
        }                                                                           \
        const uint32_t sb = sb0 + (uint32_t)((c & 1) * STG_BYTES);                  \
        _Pragma("unroll")                                                           \
        for (int ks = 0; ks < 2; ks++) {                                            \
            const uint32_t ko = (uint32_t)(ks * 32);                                \
            uint32_t a0[4][4], a1[4][4], b0[2][4], b1[2][4];                        \
            _Pragma("unroll") for (int mi = 0; mi < 4; mi++)                        \
                ldsm4(a0[mi], sb + STG_A + aOff + mi * 1280 + ko);                  \
            _Pragma("unroll") for (int nj = 0; nj < 2; nj++)                        \
                ldsm4(b0[nj], sb + STG_B + bOff + nj * 1280 + ko);                  \
            _Pragma("unroll") for (int nj = 0; nj < 2; nj++)                        \
                ldsm4(b1[nj], sb + STG_BL + bOff + nj * 1280 + ko);                 \
            _Pragma("unroll") for (int mi = 0; mi < 4; mi++)                        \
                ldsm4(a1[mi], sb + STG_AL + aOff + mi * 1280 + ko);                 \
            _Pragma("unroll") for (int mi = 0; mi < 4; mi++)                        \
            _Pragma("unroll") for (int ni = 0; ni < 4; ni++)                        \
                mma16816(acc[mi][ni], a0[mi], &b0[ni >> 1][(ni & 1) * 2]);          \
            _Pragma("unroll") for (int mi = 0; mi < 4; mi++)                        \
            _Pragma("unroll") for (int ni = 0; ni < 4; ni++)                        \
                mma16816(acc[mi][ni], a0[mi], &b1[ni >> 1][(ni & 1) * 2]);          \
            _Pragma("unroll") for (int mi = 0; mi < 4; mi++)                        \
            _Pragma("unroll") for (int ni = 0; ni < 4; ni++)                        \
                mma16816(acc[mi][ni], a1[mi], &b0[ni >> 1][(ni & 1) * 2]);          \
        }                                                                           \
    }

// ================= GEMM #2: out-proj (float out + bias) =================
__global__ __launch_bounds__(256, 2) void gemm_tc(
    const __nv_bfloat16* __restrict__ Ah, const __nv_bfloat16* __restrict__ Al,
    const __nv_bfloat16* __restrict__ Bh, const __nv_bfloat16* __restrict__ Bl,
    const float* __restrict__ bias, float* __restrict__ C, int N, int K)
{
    extern __shared__ char smem[];
    const int tid = threadIdx.x;
    const int lane = tid & 31;
    const int wid = tid >> 5;
    const int wm = wid & 1;
    const int wn = wid >> 1;
    const int bm = blockIdx.y * 128;
    const int bn = blockIdx.x * 128;

    GEMM_MAINLOOP(Ah, Al, Bh, Bl, K)

    const int rbase = bm + wm * 64 + (lane >> 2);
    const int cbase = bn + wn * 32 + (lane & 3) * 2;
#pragma unroll
    for (int mi = 0; mi < 4; mi++) {
#pragma unroll
        for (int ni = 0; ni < 4; ni++) {
            const int col = cbase + ni * 8;
            const float2 bv = *(const float2*)(bias + col);
            const int r0 = rbase + mi * 16;
            float2 o0, o1;
            o0.x = acc[mi][ni][0] + bv.x; o0.y = acc[mi][ni][1] + bv.y;
            o1.x = acc[mi][ni][2] + bv.x; o1.y = acc[mi][ni][3] + bv.y;
            *(float2*)(C + (size_t)r0 * N + col) = o0;
            *(float2*)(C + (size_t)(r0 + 8) * N + col) = o1;
        }
    }
}

// ================= GEMM #1: QKV projection + fused RoPE (table) =================
__global__ __launch_bounds__(256, 2) void gemm_qkv_rope(
    const __nv_bfloat16* __restrict__ Ah, const __nv_bfloat16* __restrict__ Al,
    const __nv_bfloat16* __restrict__ Bh, const __nv_bfloat16* __restrict__ Bl,
    const float* __restrict__ bias)
{
    extern __shared__ char smem[];
    const int tid = threadIdx.x;
    const int lane = tid & 31;
    const int wid = tid >> 5;
    const int wm = wid & 1;
    const int wn = wid >> 1;
    const int bm = blockIdx.y * 128;
    const int bn = blockIdx.x * 128;
    const int K = 2048;

    GEMM_MAINLOOP(Ah, Al, Bh, Bl, K)

    __syncthreads();

    const int seg   = bn >> 11;          // 0=Q 1=K 2=V
    const int head  = (bn & 2047) >> 7;
    const int bidx  = bm >> 11;
    const int s_base = bm & 2047;
    const int bhh   = bidx * 16 + head;

    __nv_bfloat16* sh_hi = (__nv_bfloat16*)smem;
    __nv_bfloat16* sh_lo = (__nv_bfloat16*)(smem + 32768);

    const int rl = wm * 64 + (lane >> 2);
    const int cb = wn * 32 + (lane & 3) * 2;
    const float qscale = 0.08838834764831845f;

#pragma unroll
    for (int mi = 0; mi < 4; mi++) {
#pragma unroll
        for (int ni = 0; ni < 4; ni++) {
            const int c = cb + ni * 8;
            const float b0 = bias[bn + c], b1 = bias[bn + c + 1];
            float v0 = acc[mi][ni][0] + b0, v1 = acc[mi][ni][1] + b1;
            float w0 = acc[mi][ni][2] + b0, w1 = acc[mi][ni][3] + b1;
            const int r0 = rl + mi * 16, r1 = r0 + 8;
            if (seg < 2) {
                const int j = c >> 1;
                const float2 t0 = g_rope[(s_base + r0) * 64 + j];
                const float2 t1 = g_rope[(s_base + r1) * 64 + j];
                float a0 = v0 * t0.x - v1 * t0.y, o0 = v0 * t0.y + v1 * t0.x;
                float a1 = w0 * t1.x - w1 * t1.y, o1 = w0 * t1.y + w1 * t1.x;
                if (seg == 0) { a0 *= qscale; o0 *= qscale; a1 *= qscale; o1 *= qscale; }
                stage_split(sh_hi, sh_lo, r0 * 128 + j,      a0);
                stage_split(sh_hi, sh_lo, r0 * 128 + j + 64, o0);
                stage_split(sh_hi, sh_lo, r1 * 128 + j,      a1);
                stage_split(sh_hi, sh_lo, r1 * 128 + j + 64, o1);
            } else {
                stage_split(sh_hi, sh_lo, c * 128 + r0,       v0);
                stage_split(sh_hi, sh_lo, (c + 1) * 128 + r0, v1);
                stage_split(sh_hi, sh_lo, c * 128 + r1,       w0);
                stage_split(sh_hi, sh_lo, (c + 1) * 128 + r1, w1);
            }
        }
    }
    __syncthreads();

    if (seg < 2) {
        __nv_bfloat16* Hd = (seg == 0) ? g_qh : g_kh;
        __nv_bfloat16* Ld = (seg == 0) ? g_ql : g_kl;
        for (int i = tid; i < 2048; i += 256) {
            const int row = i >> 4, q = i & 15;
            const size_t eo = ((size_t)bhh * 2048 + s_base + row) * 128 + q * 8;
            *(uint4*)(Hd + eo) = *(const uint4*)(sh_hi + row * 128 + q * 8);
            *(uint4*)(Ld + eo) = *(const uint4*)(sh_lo + row * 128 + q * 8);
        }
    } else {
        for (int i = tid; i < 2048; i += 256) {
            const int d = i >> 4, q = i & 15;
            const size_t eo = ((size_t)(bhh * 128 + d)) * 2048 + s_base + q * 8;
            *(uint4*)(g_vth + eo) = *(const uint4*)(sh_hi + d * 128 + q * 8);
            *(uint4*)(g_vtl + eo) = *(const uint4*)(sh_lo + d * 128 + q * 8);
        }
    }
}

// ================= flash attention: Q in regs, P in regs, cp.async K/V =================
#define AT_ROW   272
#define AT_VROW  144
// K stage s: s*34816 (hi), +17408 (lo).  V stage s: 69632 + s*36864 (hi), +18432 (lo)
#define AT_SMEM  143360

__global__ __launch_bounds__(256) void attn_tc()
{
    extern __shared__ char sm[];
    const uint32_t sb = smem_u32(sm);
    const int tid = threadIdx.x;
    const int lane = tid & 31;
    const int w = tid >> 5;
    const int qb = blockIdx.x;
    const int bh = blockIdx.y;

    const size_t hbase = (size_t)bh * 2048 * 128;
    const uint4* Qh = (const uint4*)(g_qh + hbase + (size_t)qb * 128 * 128);
    const uint4* Ql = (const uint4*)(g_ql + hbase + (size_t)qb * 128 * 128);
    const __nv_bfloat16* Khp = g_kh + hbase;
    const __nv_bfloat16* Klp = g_kl + hbase;
    const __nv_bfloat16* Vth = g_vth + (size_t)bh * 128 * 2048;
    const __nv_bfloat16* Vtl = g_vtl + (size_t)bh * 128 * 2048;

    // stage Q into K-stage buffers temporarily
    for (int i = tid; i < 2048; i += 256) {
        const uint32_t off = (uint32_t)((i >> 4) * AT_ROW + (i & 15) * 16);
        *(uint4*)(sm + off) = Qh[i];
        *(uint4*)(sm + 34816 + off) = Ql[i];
    }
    __syncthreads();

    const uint32_t aOff = (uint32_t)((w * 16 + (lane & 15)) * AT_ROW + ((lane >> 4) << 4));
    uint32_t qfh[8][4], qfl[8][4];
#pragma unroll
    for (int kk = 0; kk < 8; kk++) {
        ldsm4(qfh[kk], sb + aOff + kk * 32);
        ldsm4(qfl[kk], sb + 34816 + aOff + kk * 32);
    }
    __syncthreads();

    const uint32_t bOff = (uint32_t)(((lane & 7) + ((lane >> 4) << 3)) * AT_ROW
                                     + (((lane >> 3) & 1) << 4));
    const uint32_t bV   = (uint32_t)(((lane & 7) + ((lane >> 4) << 3)) * AT_VROW
                                     + (((lane >> 3) & 1) << 4));

    float O[16][4];
#pragma unroll
    for (int i = 0; i < 16; i++)
#pragma unroll
        for (int j = 0; j < 4; j++) O[i][j] = 0.0f;
    float m0 = -30000.0f, m1 = -30000.0f, l0 = 0.0f, l1 = 0.0f;
    const int g = lane >> 2, lam = lane & 3;

    auto load_chunk = [&](int kc, int st) {
        const uint32_t kbase = sb + (uint32_t)(st * 34816);
        const uint32_t vbase = sb + 69632u + (uint32_t)(st * 36864);
#pragma unroll
        for (int t = 0; t < 4; t++) {
            const int i = tid + t * 256;
            const int kr = i >> 4, kq = i & 15;
            cp16(kbase + kr * AT_ROW + kq * 16,         Khp + (size_t)(kc + kr) * 128 + kq * 8);
            cp16(kbase + 17408 + kr * AT_ROW + kq * 16, Klp + (size_t)(kc + kr) * 128 + kq * 8);
            const int vr = i >> 3, vq = i & 7;
            cp16(vbase + vr * AT_VROW + vq * 16,         Vth + (size_t)vr * 2048 + kc + vq * 8);
            cp16(vbase + 18432 + vr * AT_VROW + vq * 16, Vtl + (size_t)vr * 2048 + kc + vq * 8);
        }
    };

    load_chunk(0, 0);
    CP_COMMIT();

    for (int cidx = 0; cidx < 32; cidx++) {
        CP_WAIT0();
        __syncthreads();
        if (cidx + 1 < 32) {
            load_chunk((cidx + 1) * 64, (cidx + 1) & 1);
            CP_COMMIT();
        }
        const uint32_t kst = sb + (uint32_t)((cidx & 1) * 34816);
        const uint32_t vst = sb + 69632u + (uint32_t)((cidx & 1) * 36864);

        // ---- S = Q @ K^T (3-term split) ----
        float S[8][4];
#pragma unroll
        for (int t = 0; t < 8; t++)
#pragma unroll
            for (int j = 0; j < 4; j++) S[t][j] = 0.0f;

#pragma unroll
        for (int kk = 0; kk < 8; kk++) {
#pragma unroll
            for (int kg = 0; kg < 4; kg++) {
                uint32_t kbh[4], kbl[4];
                ldsm4(kbh, kst + bOff + kg * (16 * AT_ROW) + kk * 32);
                ldsm4(kbl, kst + 17408 + bOff + kg * (16 * AT_ROW) + kk * 32);
                mma16816(S[2 * kg],     qfh[kk], kbh + 0);
                mma16816(S[2 * kg + 1], qfh[kk], kbh + 2);
                mma16816(S[2 * kg],     qfh[kk], kbl + 0);
                mma16816(S[2 * kg + 1], qfh[kk], kbl + 2);
                mma16816(S[2 * kg],     qfl[kk], kbh + 0);
                mma16816(S[2 * kg + 1], qfl[kk], kbh + 2);
            }
        }

        // ---- online softmax ----
        float mx0 = -30000.0f, mx1 = -30000.0f;
#pragma unroll
        for (int t = 0; t < 8; t++) {
            mx0 = fmaxf(mx0, fmaxf(S[t][0], S[t][1]));
            mx1 = fmaxf(mx1, fmaxf(S[t][2], S[t][3]));
        }
        mx0 = fmaxf(mx0, __shfl_xor_sync(0xffffffff, mx0, 1));
        mx0 = fmaxf(mx0, __shfl_xor_sync(0xffffffff, mx0, 2));
        mx1 = fmaxf(mx1, __shfl_xor_sync(0xffffffff, mx1, 1));
        mx1 = fmaxf(mx1, __shfl_xor_sync(0xffffffff, mx1, 2));

        const float nm0 = fmaxf(m0, mx0);
        const float nm1 = fmaxf(m1, mx1);
        const float al0 = __expf(fminf(m0 - nm0, 0.0f));
        const float al1 = __expf(fminf(m1 - nm1, 0.0f));
        m0 = nm0; m1 = nm1;

        float s0 = 0.0f, s1 = 0.0f;
#pragma unroll
        for (int t = 0; t < 8; t++) {
            S[t][0] = __expf(fminf(S[t][0] - m0, 0.0f));
            S[t][1] = __expf(fminf(S[t][1] - m0, 0.0f));
            S[t][2] = __expf(fminf(S[t][2] - m1, 0.0f));
            S[t][3] = __expf(fminf(S[t][3] - m1, 0.0f));
            s0 += S[t][0] + S[t][1];
            s1 += S[t][2] + S[t][3];
        }
        l0 = l0 * al0 + s0;
        l1 = l1 * al1 + s1;
#pragma unroll
        for (int nt = 0; nt < 16; nt++) {
            O[nt][0] *= al0; O[nt][1] *= al0;
            O[nt][2] *= al1; O[nt][3] *= al1;
        }

        // ---- O += P @ V, P converted directly in registers ----
        // C-accumulator layout of [S[2kt], S[2kt+1]] == A-fragment layout for m16k16
#pragma unroll
        for (int kt = 0; kt < 4; kt++) {
            uint32_t ph[4], pl[4];
            {
                __nv_bfloat162 h;
                h = __floats2bfloat162_rn(S[2 * kt][0], S[2 * kt][1]);
                ph[0] = bf2_bits(h);
                pl[0] = bf2_bits(__floats2bfloat162_rn(S[2 * kt][0] - __bfloat162float(h.x),
                                                       S[2 * kt][1] - __bfloat162float(h.y)));
                h = __floats2bfloat162_rn(S[2 * kt][2], S[2 * kt][3]);
                ph[1] = bf2_bits(h);
                pl[1] = bf2_bits(__floats2bfloat162_rn(S[2 * kt][2] - __bfloat162float(h.x),
                                                       S[2 * kt][3] - __bfloat162float(h.y)));
                h = __floats2bfloat162_rn(S[2 * kt + 1][0], S[2 * kt + 1][1]);
                ph[2] = bf2_bits(h);
                pl[2] = bf2_bits(__floats2bfloat162_rn(S[2 * kt + 1][0] - __bfloat162float(h.x),
                                                       S[2 * kt + 1][1] - __bfloat162float(h.y)));
                h = __floats2bfloat162_rn(S[2 * kt + 1][2], S[2 * kt + 1][3]);
                ph[3] = bf2_bits(h);
                pl[3] = bf2_bits(__floats2bfloat162_rn(S[2 * kt + 1][2] - __bfloat162float(h.x),
                                                       S[2 * kt + 1][3] - __bfloat162float(h.y)));
            }
#pragma unroll
            for (int j = 0; j < 8; j++) {
                uint32_t vbh[4], vbl[4];
                ldsm4(vbh, vst + bV + j * (16 * AT_VROW) + kt * 32);
                ldsm4(vbl, vst + 18432 + bV + j * (16 * AT_VROW) + kt * 32);
                mma16816(O[2 * j],     ph, vbh + 0);
                mma16816(O[2 * j + 1], ph, vbh + 2);
                mma16816(O[2 * j],     ph, vbl + 0);
                mma16816(O[2 * j + 1], ph, vbl + 2);
                mma16816(O[2 * j],     pl, vbh + 0);
                mma16816(O[2 * j + 1], pl, vbh + 2);
            }
        }
    }

    // ---- epilogue ----
    l0 += __shfl_xor_sync(0xffffffff, l0, 1);
    l0 += __shfl_xor_sync(0xffffffff, l0, 2);
    l1 += __shfl_xor_sync(0xffffffff, l1, 1);
    l1 += __shfl_xor_sync(0xffffffff, l1, 2);
    const float inv0 = 1.0f / l0;
    const float inv1 = 1.0f / l1;

    const int bb = bh >> 4, hh2 = bh & 15;
    const int row0 = qb * 128 + w * 16 + g;
    const size_t base0 = (size_t)(bb * 2048 + row0) * 2048 + hh2 * 128 + lam * 2;
    const size_t base1 = base0 + (size_t)8 * 2048;

#pragma unroll
    for (int nt = 0; nt < 16; nt++) {
        float x0 = O[nt][0] * inv0, x1 = O[nt][1] * inv0;
        __nv_bfloat162 hx = __floats2bfloat162_rn(x0, x1);
        __nv_bfloat162 lx = __floats2bfloat162_rn(x0 - __bfloat162float(hx.x),
                                                  x1 - __bfloat162float(hx.y));
        *(uint32_t*)(g_att_hi + base0 + nt * 8) = bf2_bits(hx);
        *(uint32_t*)(g_att_lo + base0 + nt * 8) = bf2_bits(lx);

        float x2 = O[nt][2] * inv1, x3 = O[nt][3] * inv1;
        hx = __floats2bfloat162_rn(x2, x3);
        lx = __floats2bfloat162_rn(x2 - __bfloat162float(hx.x),
                                   x3 - __bfloat162float(hx.y));
        *(uint32_t*)(g_att_hi + base1 + nt * 8) = bf2_bits(hx);
        *(uint32_t*)(g_att_lo + base1 + nt * 8) = bf2_bits(lx);
    }
}

// ================= launch =================
extern "C" void kernel_launch(void* const* d_in, const int* in_sizes, int n_in,
                              void* d_out, int out_size)
{
    const float* x    = (const float*)d_in[0];
    const float* Wqkv = (const float*)d_in[1];
    const float* bqkv = (const float*)d_in[2];
    const float* Wo   = (const float*)d_in[3];
    const float* bo   = (const float*)d_in[4];
    float* out = (float*)d_out;

    __nv_bfloat16 *xh, *xl, *ah, *al, *wqh, *wql, *woh, *wol;
    cudaGetSymbolAddress((void**)&xh, g_x_hi);
    cudaGetSymbolAddress((void**)&xl, g_x_lo);
    cudaGetSymbolAddress((void**)&ah, g_att_hi);
    cudaGetSymbolAddress((void**)&al, g_att_lo);
    cudaGetSymbolAddress((void**)&wqh, g_WqkvT_hi);
    cudaGetSymbolAddress((void**)&wql, g_WqkvT_lo);
    cudaGetSymbolAddress((void**)&woh, g_WoT_hi);
    cudaGetSymbolAddress((void**)&wol, g_WoT_lo);

    cudaFuncSetAttribute(gemm_tc, cudaFuncAttributeMaxDynamicSharedMemorySize, G_SMEM);
    cudaFuncSetAttribute(gemm_qkv_rope, cudaFuncAttributeMaxDynamicSharedMemorySize, G_SMEM);
    cudaFuncSetAttribute(attn_tc, cudaFuncAttributeMaxDynamicSharedMemorySize, AT_SMEM);

    // prep
    rope_table_kernel<<<(2048 * 64) / 256, 256>>>();
    split_convert<<<(4096 * 2048) / 256, 256>>>(x, xh, xl, 4096 * 2048);
    transpose_split<<<dim3(6144 / 32, 2048 / 32), dim3(32, 8)>>>(Wqkv, wqh, wql, 2048, 6144);
    transpose_split<<<dim3(2048 / 32, 2048 / 32), dim3(32, 8)>>>(Wo, woh, wol, 2048, 2048);

    // 1) QKV projection + fused RoPE/head-split/V-transpose
    gemm_qkv_rope<<<dim3(48, 32), 256, G_SMEM>>>(xh, xl, wqh, wql, bqkv);

    // 2) Tensor-core flash attention
    attn_tc<<<dim3(16, 32), 256, AT_SMEM>>>();

    // 3) Output projection
    gemm_tc<<<dim3(16, 32), 256, G_SMEM>>>(ah, al, woh, wol, bo, out, 2048, 2048);
}